// round 1
// baseline (speedup 1.0000x reference)
#include <cuda_runtime.h>
#include <math.h>

#define B_  4
#define NQ  512
#define NC  2048
#define DQ  1024
#define DC  768
#define CC  1024
#define HH  16
#define HD  64
#define LL  2
#define FF  4096
#define EPSLN 1e-5f

// ---------------- scratch (no allocations allowed) ----------------
__device__ float g_bufQ [B_*NQ*CC];        // 8 MB   running residual stream
__device__ float g_bufC [B_*NC*CC];        // 32 MB  projected context
__device__ float g_bufQN[B_*NQ*CC];        // 8 MB   LN output
__device__ float g_bufQH[B_*NQ*CC];        // 8 MB   per-layer Q heads
__device__ float g_bufKV[B_*NC*2*CC];      // 64 MB  per-layer KV
__device__ float g_bufO [B_*NQ*CC];        // 8 MB   attention output
__device__ float g_bufF [B_*NQ*FF];        // 32 MB  FFN hidden

// ---------------- generic SGEMM: out = A[M,K] @ W[K,N] + bias (+gelu) (+resid) ----------------
// 128x128 block tile, BK=8, 256 threads, 8x8 per-thread register tile.
__global__ __launch_bounds__(256) void gemm_kernel(
    const float* __restrict__ A, const float* __restrict__ W,
    const float* __restrict__ bias, const float* __restrict__ resid,
    float* __restrict__ out, int M, int N, int K, int do_gelu)
{
    __shared__ float As[8][128];
    __shared__ float Bs[8][128];
    const int tid = threadIdx.x;
    const int bm  = blockIdx.y * 128;
    const int bn  = blockIdx.x * 128;
    const int ty  = tid >> 4;    // 0..15
    const int tx  = tid & 15;    // 0..15

    const int arow = tid >> 1;            // 0..127
    const int acol = (tid & 1) * 4;       // 0 or 4
    const int brow = tid >> 5;            // 0..7
    const int bcol = (tid & 31) * 4;      // 0..124

    const float* Ap = A + (size_t)(bm + arow) * K + acol;
    const float* Wp = W + (size_t)brow * N + bn + bcol;

    float acc[8][8];
    #pragma unroll
    for (int i = 0; i < 8; i++)
        #pragma unroll
        for (int j = 0; j < 8; j++) acc[i][j] = 0.f;

    for (int kt = 0; kt < K; kt += 8) {
        float4 a4 = *(const float4*)Ap; Ap += 8;
        float4 b4 = *(const float4*)Wp; Wp += (size_t)8 * N;
        As[acol + 0][arow] = a4.x;
        As[acol + 1][arow] = a4.y;
        As[acol + 2][arow] = a4.z;
        As[acol + 3][arow] = a4.w;
        *(float4*)&Bs[brow][bcol] = b4;
        __syncthreads();
        #pragma unroll
        for (int kk = 0; kk < 8; kk++) {
            float ra[8], rb[8];
            *(float4*)(ra)     = *(const float4*)&As[kk][ty*8];
            *(float4*)(ra + 4) = *(const float4*)&As[kk][ty*8 + 4];
            *(float4*)(rb)     = *(const float4*)&Bs[kk][tx*8];
            *(float4*)(rb + 4) = *(const float4*)&Bs[kk][tx*8 + 4];
            #pragma unroll
            for (int i = 0; i < 8; i++)
                #pragma unroll
                for (int j = 0; j < 8; j++)
                    acc[i][j] = fmaf(ra[i], rb[j], acc[i][j]);
        }
        __syncthreads();
    }

    #pragma unroll
    for (int i = 0; i < 8; i++) {
        int row = bm + ty*8 + i;
        #pragma unroll
        for (int j = 0; j < 8; j++) {
            int col = bn + tx*8 + j;
            float v = acc[i][j] + bias[col];
            if (do_gelu) v = 0.5f * v * (1.f + erff(v * 0.70710678118654752f));
            if (resid)   v += resid[(size_t)row * N + col];
            out[(size_t)row * N + col] = v;
        }
    }
}

// ---------------- LayerNorm over last dim (CC=1024), one block per row ----------------
__global__ __launch_bounds__(256) void ln_kernel(
    const float* __restrict__ x, const float* __restrict__ g,
    const float* __restrict__ b, float* __restrict__ y)
{
    __shared__ float red[256];
    const int row = blockIdx.x;
    const int tid = threadIdx.x;
    const float* xr = x + (size_t)row * CC;

    float v[4];
    float s = 0.f;
    #pragma unroll
    for (int i = 0; i < 4; i++) { v[i] = xr[tid + i*256]; s += v[i]; }
    red[tid] = s; __syncthreads();
    for (int off = 128; off > 0; off >>= 1) {
        if (tid < off) red[tid] += red[tid + off];
        __syncthreads();
    }
    const float mean = red[0] * (1.f / CC);
    __syncthreads();

    float sq = 0.f;
    #pragma unroll
    for (int i = 0; i < 4; i++) { float d = v[i] - mean; sq += d * d; }
    red[tid] = sq; __syncthreads();
    for (int off = 128; off > 0; off >>= 1) {
        if (tid < off) red[tid] += red[tid + off];
        __syncthreads();
    }
    const float rstd = rsqrtf(red[0] * (1.f / CC) + EPSLN);

    #pragma unroll
    for (int i = 0; i < 4; i++) {
        int c = tid + i*256;
        y[(size_t)row * CC + c] = (v[i] - mean) * rstd * g[c] + b[c];
    }
}

// ---------------- fused flash-style attention ----------------
// grid: (NQ/64, H, B), 256 threads. Each block: 64 q-rows for one (b,h).
// Online softmax over NC in 64-key chunks. smem tiles stride 65 (bank-conflict pad).
#define SR 65
__global__ __launch_bounds__(256) void attn_kernel(
    const float* __restrict__ QH, const float* __restrict__ KV,
    const int* __restrict__ mask, float* __restrict__ OUT)
{
    extern __shared__ float sm[];
    float* Qs = sm;                  // 64 x 65
    float* Ks = Qs + 64*SR;          // 64 x 65
    float* Vs = Ks + 64*SR;          // 64 x 65
    float* Ps = Vs + 64*SR;          // 64 x 65
    float* Mv = Ps + 64*SR;          // 64

    const int tid = threadIdx.x;
    const int b = blockIdx.z, h = blockIdx.y;
    const int q0 = blockIdx.x * 64;

    for (int i = tid; i < 64*64; i += 256) {
        int r = i >> 6, d = i & 63;
        Qs[r*SR + d] = QH[(size_t)(b*NQ + q0 + r) * CC + h*HD + d];
    }

    const int r  = tid >> 2;          // q-row 0..63
    const int c0 = (tid & 3) * 16;    // 16-wide column group

    float m = -1e30f, l = 0.f;
    float acc[16];
    #pragma unroll
    for (int j = 0; j < 16; j++) acc[j] = 0.f;

    for (int kc = 0; kc < NC; kc += 64) {
        __syncthreads();
        for (int i = tid; i < 64*64; i += 256) {
            int rr = i >> 6, d = i & 63;
            size_t base = (size_t)(b*NC + kc + rr) * (2*CC) + h*HD + d;
            Ks[rr*SR + d] = KV[base];
            Vs[rr*SR + d] = KV[base + CC];
        }
        if (tid < 64) Mv[tid] = (mask[b*NC + kc + tid] != 0) ? 0.f : -1e30f;
        __syncthreads();

        // S chunk: s[j] = q[r] . k[c0+j]
        float s[16];
        #pragma unroll
        for (int j = 0; j < 16; j++) s[j] = 0.f;
        #pragma unroll 8
        for (int d = 0; d < 64; d++) {
            float qd = Qs[r*SR + d];
            #pragma unroll
            for (int j = 0; j < 16; j++)
                s[j] = fmaf(qd, Ks[(c0 + j)*SR + d], s[j]);
        }

        float cm = -1e30f;
        #pragma unroll
        for (int j = 0; j < 16; j++) {
            s[j] = s[j] * 0.125f + Mv[c0 + j];   // scale = HD^-0.5, mask adds -1e30
            cm = fmaxf(cm, s[j]);
        }
        cm = fmaxf(cm, __shfl_xor_sync(0xffffffffu, cm, 1));
        cm = fmaxf(cm, __shfl_xor_sync(0xffffffffu, cm, 2));
        const float nm = fmaxf(m, cm);
        const float alpha = __expf(m - nm);

        float psum = 0.f;
        #pragma unroll
        for (int j = 0; j < 16; j++) {
            float p = __expf(s[j] - nm);
            Ps[r*SR + c0 + j] = p;
            psum += p;
        }
        psum += __shfl_xor_sync(0xffffffffu, psum, 1);
        psum += __shfl_xor_sync(0xffffffffu, psum, 2);
        l = l * alpha + psum;
        #pragma unroll
        for (int j = 0; j < 16; j++) acc[j] *= alpha;
        __syncwarp();

        // O += P @ V
        #pragma unroll 4
        for (int k = 0; k < 64; k++) {
            float p = Ps[r*SR + k];
            #pragma unroll
            for (int j = 0; j < 16; j++)
                acc[j] = fmaf(p, Vs[k*SR + c0 + j], acc[j]);
        }
        m = nm;
    }

    const float inv = 1.f / l;
    #pragma unroll
    for (int j = 0; j < 16; j++)
        OUT[(size_t)(b*NQ + q0 + r) * CC + h*HD + c0 + j] = acc[j] * inv;
}

// ---------------- orchestration ----------------
extern "C" void kernel_launch(void* const* d_in, const int* in_sizes, int n_in,
                              void* d_out, int out_size)
{
    const float* query   = (const float*)d_in[0];
    const float* context = (const float*)d_in[1];
    const int*   cmask   = (const int*)  d_in[2];
    const float* Wqp   = (const float*)d_in[3];
    const float* bqp   = (const float*)d_in[4];
    const float* Wcp   = (const float*)d_in[5];
    const float* bcp   = (const float*)d_in[6];
    const float* Wq    = (const float*)d_in[7];
    const float* bq    = (const float*)d_in[8];
    const float* Wkv   = (const float*)d_in[9];
    const float* bkv   = (const float*)d_in[10];
    const float* Wo    = (const float*)d_in[11];
    const float* bo    = (const float*)d_in[12];
    const float* g1    = (const float*)d_in[13];
    const float* beta1 = (const float*)d_in[14];
    const float* W1    = (const float*)d_in[15];
    const float* bf1   = (const float*)d_in[16];
    const float* W2    = (const float*)d_in[17];
    const float* bf2   = (const float*)d_in[18];
    const float* g2    = (const float*)d_in[19];
    const float* beta2 = (const float*)d_in[20];
    const float* gf    = (const float*)d_in[21];
    const float* betaf = (const float*)d_in[22];
    float* out = (float*)d_out;

    float *bufQ, *bufC, *bufQN, *bufQH, *bufKV, *bufO, *bufF;
    cudaGetSymbolAddress((void**)&bufQ,  g_bufQ);
    cudaGetSymbolAddress((void**)&bufC,  g_bufC);
    cudaGetSymbolAddress((void**)&bufQN, g_bufQN);
    cudaGetSymbolAddress((void**)&bufQH, g_bufQH);
    cudaGetSymbolAddress((void**)&bufKV, g_bufKV);
    cudaGetSymbolAddress((void**)&bufO,  g_bufO);
    cudaGetSymbolAddress((void**)&bufF,  g_bufF);

    const int smem_attn = (4*64*SR + 64) * (int)sizeof(float);  // 66816 B
    cudaFuncSetAttribute(attn_kernel, cudaFuncAttributeMaxDynamicSharedMemorySize, smem_attn);

    const dim3 blk(256);
    const int MQ = B_ * NQ;   // 2048
    const int MC = B_ * NC;   // 8192

    // input projections
    gemm_kernel<<<dim3(CC/128, MQ/128), blk>>>(query,   Wqp, bqp, nullptr, bufQ, MQ, CC, DQ, 0);
    gemm_kernel<<<dim3(CC/128, MC/128), blk>>>(context, Wcp, bcp, nullptr, bufC, MC, CC, DC, 0);

    for (int l = 0; l < LL; l++) {
        ln_kernel<<<MQ, 256>>>(bufQ, g1 + l*CC, beta1 + l*CC, bufQN);
        gemm_kernel<<<dim3(CC/128,   MQ/128), blk>>>(bufQN, Wq  + (size_t)l*CC*CC,   bq  + l*CC,   nullptr, bufQH, MQ, CC,   CC, 0);
        gemm_kernel<<<dim3(2*CC/128, MC/128), blk>>>(bufC,  Wkv + (size_t)l*CC*2*CC, bkv + l*2*CC, nullptr, bufKV, MC, 2*CC, CC, 0);
        attn_kernel<<<dim3(NQ/64, HH, B_), 256, smem_attn>>>(bufQH, bufKV, cmask, bufO);
        gemm_kernel<<<dim3(CC/128, MQ/128), blk>>>(bufO, Wo + (size_t)l*CC*CC, bo + l*CC, bufQ, bufQ, MQ, CC, CC, 0);
        ln_kernel<<<MQ, 256>>>(bufQ, g2 + l*CC, beta2 + l*CC, bufQN);
        gemm_kernel<<<dim3(FF/128, MQ/128), blk>>>(bufQN, W1 + (size_t)l*CC*FF, bf1 + l*FF, nullptr, bufF, MQ, FF, CC, 1);
        gemm_kernel<<<dim3(CC/128, MQ/128), blk>>>(bufF,  W2 + (size_t)l*FF*CC, bf2 + l*CC, bufQ,    bufQ, MQ, CC, FF, 0);
    }
    ln_kernel<<<MQ, 256>>>(bufQ, gf, betaf, out);
}

// round 2
// speedup vs baseline: 1.4640x; 1.4640x over previous
#include <cuda_runtime.h>
#include <math.h>

#define B_  4
#define NQ  512
#define NC  2048
#define DQ  1024
#define DC  768
#define CC  1024
#define HH  16
#define HD  64
#define LL  2
#define FF  4096
#define EPSLN 1e-5f

// ---------------- scratch (no allocations allowed) ----------------
__device__ float g_bufQ [B_*NQ*CC];
__device__ float g_bufC [B_*NC*CC];
__device__ float g_bufQN[B_*NQ*CC];
__device__ float g_bufQH[B_*NQ*CC];
__device__ float g_bufKV[B_*NC*2*CC];
__device__ float g_bufO [B_*NQ*CC];
__device__ float g_bufF [B_*NQ*FF];

// round fp32 -> tf32 (rna, unbiased), result kept in fp32 bit-pattern
__device__ __forceinline__ float f2tf(float x) {
    unsigned r;
    asm("cvt.rna.tf32.f32 %0, %1;" : "=r"(r) : "f"(x));
    return __uint_as_float(r);
}

// ---------------- TF32 tensor-core GEMM ----------------
// out[M,N] = A[M,K] @ W[K,N] + bias (+gelu) (+resid)
// 128x128 block tile, BK=32, 256 threads (8 warps as 2x4 -> warp tile 64x32).
// smem: XOR swizzle, As[m][k] / Bs[n][k] with slot = (k/4) ^ (row&7).
__global__ __launch_bounds__(256) void gemm_tf32(
    const float* __restrict__ A, const float* __restrict__ W,
    const float* __restrict__ bias, const float* __restrict__ resid,
    float* __restrict__ out, int M, int N, int K, int do_gelu)
{
    extern __shared__ float smx[];
    float* Abuf = smx;          // 2 x 4096
    float* Bbuf = smx + 8192;   // 2 x 4096

    const int tid  = threadIdx.x;
    const int lane = tid & 31;
    const int warp = tid >> 5;
    const int wm   = warp >> 1;   // 0..3  -> m offset wm*64... wait 4 wm x 64 = 256 > 128
    // NOTE: warp layout: 4 warps along M (wm 0..3, 32 rows each)? Use 2x4 instead:
    // redo: wm2 = warp & 3 (0..3) -> 32? We want warp tile 64x32: grid 2(m) x 4(n).
    const int wmi  = warp >> 2;   // 0..1 : m block of 64
    const int wni  = warp & 3;    // 0..3 : n block of 32
    const int lr   = lane >> 2;   // 0..7
    const int lc   = lane & 3;    // 0..3
    const int bm = blockIdx.y * 128;
    const int bn = blockIdx.x * 128;

    const int a_m  = tid >> 3;    // 0..31 (+32*it)
    const int a_kq = tid & 7;
    const int b_kq = tid & 7;
    const int b_nq = tid >> 3;    // 0..31

    float4 ra[4];
    float4 rb[4];

    float acc[4][4][4];
    #pragma unroll
    for (int i = 0; i < 4; i++)
        #pragma unroll
        for (int j = 0; j < 4; j++)
            #pragma unroll
            for (int k = 0; k < 4; k++) acc[i][j][k] = 0.f;

    const int ntile = K >> 5;

    // ---- prefetch tile 0 ----
    {
        const int k0 = 0;
        #pragma unroll
        for (int it = 0; it < 4; it++) {
            int m = a_m + it*32;
            ra[it] = *(const float4*)(A + (size_t)(bm + m) * K + k0 + 4*a_kq);
        }
        #pragma unroll
        for (int j = 0; j < 4; j++)
            rb[j] = *(const float4*)(W + (size_t)(k0 + 4*b_kq + j) * N + bn + 4*b_nq);
        // store A
        #pragma unroll
        for (int it = 0; it < 4; it++) {
            int m = a_m + it*32;
            int slot = a_kq ^ (m & 7);
            float4 cv = make_float4(f2tf(ra[it].x), f2tf(ra[it].y), f2tf(ra[it].z), f2tf(ra[it].w));
            *(float4*)(Abuf + m*32 + 4*slot) = cv;
        }
        // store B (transpose in regs)
        #pragma unroll
        for (int i = 0; i < 4; i++) {
            int n = 4*b_nq + i;
            int slot = b_kq ^ (n & 7);
            const float* r0 = (const float*)&rb[0];
            const float* r1 = (const float*)&rb[1];
            const float* r2 = (const float*)&rb[2];
            const float* r3 = (const float*)&rb[3];
            float4 cv = make_float4(f2tf(r0[i]), f2tf(r1[i]), f2tf(r2[i]), f2tf(r3[i]));
            *(float4*)(Bbuf + n*32 + 4*slot) = cv;
        }
    }
    __syncthreads();

    for (int t = 1; t <= ntile; t++) {
        // issue next tile's loads (if any)
        if (t < ntile) {
            const int k0 = t * 32;
            #pragma unroll
            for (int it = 0; it < 4; it++) {
                int m = a_m + it*32;
                ra[it] = *(const float4*)(A + (size_t)(bm + m) * K + k0 + 4*a_kq);
            }
            #pragma unroll
            for (int j = 0; j < 4; j++)
                rb[j] = *(const float4*)(W + (size_t)(k0 + 4*b_kq + j) * N + bn + 4*b_nq);
        }

        // compute on buffer (t-1)&1
        {
            const float* as = Abuf + ((t-1) & 1) * 4096;
            const float* bs = Bbuf + ((t-1) & 1) * 4096;
            #pragma unroll
            for (int kk = 0; kk < 4; kk++) {
                unsigned af[4][4];
                unsigned bf[4][2];
                const int s0 = 4*((2*kk)     ^ lr) + lc;
                const int s1 = 4*((2*kk + 1) ^ lr) + lc;
                #pragma unroll
                for (int fm = 0; fm < 4; fm++) {
                    int m = wmi*64 + fm*16 + lr;
                    const float* p0 = as + m*32;
                    const float* p1 = as + (m + 8)*32;
                    af[fm][0] = __float_as_uint(p0[s0]);
                    af[fm][1] = __float_as_uint(p1[s0]);
                    af[fm][2] = __float_as_uint(p0[s1]);
                    af[fm][3] = __float_as_uint(p1[s1]);
                }
                #pragma unroll
                for (int fn = 0; fn < 4; fn++) {
                    int n = wni*32 + fn*8 + lr;
                    const float* p = bs + n*32;
                    bf[fn][0] = __float_as_uint(p[s0]);
                    bf[fn][1] = __float_as_uint(p[s1]);
                }
                #pragma unroll
                for (int fm = 0; fm < 4; fm++)
                    #pragma unroll
                    for (int fn = 0; fn < 4; fn++) {
                        asm volatile(
                            "mma.sync.aligned.m16n8k8.row.col.f32.tf32.tf32.f32 "
                            "{%0,%1,%2,%3}, {%4,%5,%6,%7}, {%8,%9}, {%0,%1,%2,%3};\n"
                            : "+f"(acc[fm][fn][0]), "+f"(acc[fm][fn][1]),
                              "+f"(acc[fm][fn][2]), "+f"(acc[fm][fn][3])
                            : "r"(af[fm][0]), "r"(af[fm][1]), "r"(af[fm][2]), "r"(af[fm][3]),
                              "r"(bf[fn][0]), "r"(bf[fn][1]));
                    }
            }
        }

        // store next tile to other buffer
        if (t < ntile) {
            float* as = Abuf + (t & 1) * 4096;
            float* bs = Bbuf + (t & 1) * 4096;
            #pragma unroll
            for (int it = 0; it < 4; it++) {
                int m = a_m + it*32;
                int slot = a_kq ^ (m & 7);
                float4 cv = make_float4(f2tf(ra[it].x), f2tf(ra[it].y), f2tf(ra[it].z), f2tf(ra[it].w));
                *(float4*)(as + m*32 + 4*slot) = cv;
            }
            #pragma unroll
            for (int i = 0; i < 4; i++) {
                int n = 4*b_nq + i;
                int slot = b_kq ^ (n & 7);
                const float* r0 = (const float*)&rb[0];
                const float* r1 = (const float*)&rb[1];
                const float* r2 = (const float*)&rb[2];
                const float* r3 = (const float*)&rb[3];
                float4 cv = make_float4(f2tf(r0[i]), f2tf(r1[i]), f2tf(r2[i]), f2tf(r3[i]));
                *(float4*)(bs + n*32 + 4*slot) = cv;
            }
            __syncthreads();
        }
    }

    // ---- epilogue ----
    #pragma unroll
    for (int fm = 0; fm < 4; fm++) {
        #pragma unroll
        for (int fn = 0; fn < 4; fn++) {
            int row = bm + wmi*64 + fm*16 + lr;
            int col = bn + wni*32 + fn*8 + 2*lc;
            float2 bv = *(const float2*)(bias + col);

            float v0 = acc[fm][fn][0] + bv.x;
            float v1 = acc[fm][fn][1] + bv.y;
            float v2 = acc[fm][fn][2] + bv.x;
            float v3 = acc[fm][fn][3] + bv.y;
            if (do_gelu) {
                v0 = 0.5f * v0 * (1.f + erff(v0 * 0.70710678118654752f));
                v1 = 0.5f * v1 * (1.f + erff(v1 * 0.70710678118654752f));
                v2 = 0.5f * v2 * (1.f + erff(v2 * 0.70710678118654752f));
                v3 = 0.5f * v3 * (1.f + erff(v3 * 0.70710678118654752f));
            }
            if (resid) {
                float2 r0 = *(const float2*)(resid + (size_t)row * N + col);
                float2 r1 = *(const float2*)(resid + (size_t)(row + 8) * N + col);
                v0 += r0.x; v1 += r0.y; v2 += r1.x; v3 += r1.y;
            }
            *(float2*)(out + (size_t)row * N + col)       = make_float2(v0, v1);
            *(float2*)(out + (size_t)(row + 8) * N + col) = make_float2(v2, v3);
        }
    }
}

// ---------------- LayerNorm over last dim (CC=1024), one block per row ----------------
__global__ __launch_bounds__(256) void ln_kernel(
    const float* __restrict__ x, const float* __restrict__ g,
    const float* __restrict__ b, float* __restrict__ y)
{
    __shared__ float red[256];
    const int row = blockIdx.x;
    const int tid = threadIdx.x;
    const float* xr = x + (size_t)row * CC;

    float v[4];
    float s = 0.f;
    #pragma unroll
    for (int i = 0; i < 4; i++) { v[i] = xr[tid + i*256]; s += v[i]; }
    red[tid] = s; __syncthreads();
    for (int off = 128; off > 0; off >>= 1) {
        if (tid < off) red[tid] += red[tid + off];
        __syncthreads();
    }
    const float mean = red[0] * (1.f / CC);
    __syncthreads();

    float sq = 0.f;
    #pragma unroll
    for (int i = 0; i < 4; i++) { float d = v[i] - mean; sq += d * d; }
    red[tid] = sq; __syncthreads();
    for (int off = 128; off > 0; off >>= 1) {
        if (tid < off) red[tid] += red[tid + off];
        __syncthreads();
    }
    const float rstd = rsqrtf(red[0] * (1.f / CC) + EPSLN);

    #pragma unroll
    for (int i = 0; i < 4; i++) {
        int c = tid + i*256;
        y[(size_t)row * CC + c] = (v[i] - mean) * rstd * g[c] + b[c];
    }
}

// ---------------- fused flash-style attention (fp32, unchanged this round) ----------------
#define SR 65
__global__ __launch_bounds__(256) void attn_kernel(
    const float* __restrict__ QH, const float* __restrict__ KV,
    const int* __restrict__ mask, float* __restrict__ OUT)
{
    extern __shared__ float sm[];
    float* Qs = sm;
    float* Ks = Qs + 64*SR;
    float* Vs = Ks + 64*SR;
    float* Ps = Vs + 64*SR;
    float* Mv = Ps + 64*SR;

    const int tid = threadIdx.x;
    const int b = blockIdx.z, h = blockIdx.y;
    const int q0 = blockIdx.x * 64;

    for (int i = tid; i < 64*64; i += 256) {
        int r = i >> 6, d = i & 63;
        Qs[r*SR + d] = QH[(size_t)(b*NQ + q0 + r) * CC + h*HD + d];
    }

    const int r  = tid >> 2;
    const int c0 = (tid & 3) * 16;

    float m = -1e30f, l = 0.f;
    float acc[16];
    #pragma unroll
    for (int j = 0; j < 16; j++) acc[j] = 0.f;

    for (int kc = 0; kc < NC; kc += 64) {
        __syncthreads();
        for (int i = tid; i < 64*64; i += 256) {
            int rr = i >> 6, d = i & 63;
            size_t base = (size_t)(b*NC + kc + rr) * (2*CC) + h*HD + d;
            Ks[rr*SR + d] = KV[base];
            Vs[rr*SR + d] = KV[base + CC];
        }
        if (tid < 64) Mv[tid] = (mask[b*NC + kc + tid] != 0) ? 0.f : -1e30f;
        __syncthreads();

        float s[16];
        #pragma unroll
        for (int j = 0; j < 16; j++) s[j] = 0.f;
        #pragma unroll 8
        for (int d = 0; d < 64; d++) {
            float qd = Qs[r*SR + d];
            #pragma unroll
            for (int j = 0; j < 16; j++)
                s[j] = fmaf(qd, Ks[(c0 + j)*SR + d], s[j]);
        }

        float cm = -1e30f;
        #pragma unroll
        for (int j = 0; j < 16; j++) {
            s[j] = s[j] * 0.125f + Mv[c0 + j];
            cm = fmaxf(cm, s[j]);
        }
        cm = fmaxf(cm, __shfl_xor_sync(0xffffffffu, cm, 1));
        cm = fmaxf(cm, __shfl_xor_sync(0xffffffffu, cm, 2));
        const float nm = fmaxf(m, cm);
        const float alpha = __expf(m - nm);

        float psum = 0.f;
        #pragma unroll
        for (int j = 0; j < 16; j++) {
            float p = __expf(s[j] - nm);
            Ps[r*SR + c0 + j] = p;
            psum += p;
        }
        psum += __shfl_xor_sync(0xffffffffu, psum, 1);
        psum += __shfl_xor_sync(0xffffffffu, psum, 2);
        l = l * alpha + psum;
        #pragma unroll
        for (int j = 0; j < 16; j++) acc[j] *= alpha;
        __syncwarp();

        #pragma unroll 4
        for (int k = 0; k < 64; k++) {
            float p = Ps[r*SR + k];
            #pragma unroll
            for (int j = 0; j < 16; j++)
                acc[j] = fmaf(p, Vs[k*SR + c0 + j], acc[j]);
        }
        m = nm;
    }

    const float inv = 1.f / l;
    #pragma unroll
    for (int j = 0; j < 16; j++)
        OUT[(size_t)(b*NQ + q0 + r) * CC + h*HD + c0 + j] = acc[j] * inv;
}

// ---------------- orchestration ----------------
extern "C" void kernel_launch(void* const* d_in, const int* in_sizes, int n_in,
                              void* d_out, int out_size)
{
    const float* query   = (const float*)d_in[0];
    const float* context = (const float*)d_in[1];
    const int*   cmask   = (const int*)  d_in[2];
    const float* Wqp   = (const float*)d_in[3];
    const float* bqp   = (const float*)d_in[4];
    const float* Wcp   = (const float*)d_in[5];
    const float* bcp   = (const float*)d_in[6];
    const float* Wq    = (const float*)d_in[7];
    const float* bq    = (const float*)d_in[8];
    const float* Wkv   = (const float*)d_in[9];
    const float* bkv   = (const float*)d_in[10];
    const float* Wo    = (const float*)d_in[11];
    const float* bo    = (const float*)d_in[12];
    const float* g1    = (const float*)d_in[13];
    const float* beta1 = (const float*)d_in[14];
    const float* W1    = (const float*)d_in[15];
    const float* bf1   = (const float*)d_in[16];
    const float* W2    = (const float*)d_in[17];
    const float* bf2   = (const float*)d_in[18];
    const float* g2    = (const float*)d_in[19];
    const float* beta2 = (const float*)d_in[20];
    const float* gf    = (const float*)d_in[21];
    const float* betaf = (const float*)d_in[22];
    float* out = (float*)d_out;

    float *bufQ, *bufC, *bufQN, *bufQH, *bufKV, *bufO, *bufF;
    cudaGetSymbolAddress((void**)&bufQ,  g_bufQ);
    cudaGetSymbolAddress((void**)&bufC,  g_bufC);
    cudaGetSymbolAddress((void**)&bufQN, g_bufQN);
    cudaGetSymbolAddress((void**)&bufQH, g_bufQH);
    cudaGetSymbolAddress((void**)&bufKV, g_bufKV);
    cudaGetSymbolAddress((void**)&bufO,  g_bufO);
    cudaGetSymbolAddress((void**)&bufF,  g_bufF);

    const int smem_gemm = 16384 * (int)sizeof(float);           // 64 KB
    cudaFuncSetAttribute(gemm_tf32, cudaFuncAttributeMaxDynamicSharedMemorySize, smem_gemm);
    const int smem_attn = (4*64*SR + 64) * (int)sizeof(float);  // 66816 B
    cudaFuncSetAttribute(attn_kernel, cudaFuncAttributeMaxDynamicSharedMemorySize, smem_attn);

    const dim3 blk(256);
    const int MQ = B_ * NQ;   // 2048
    const int MC = B_ * NC;   // 8192

    gemm_tf32<<<dim3(CC/128, MQ/128), blk, smem_gemm>>>(query,   Wqp, bqp, nullptr, bufQ, MQ, CC, DQ, 0);
    gemm_tf32<<<dim3(CC/128, MC/128), blk, smem_gemm>>>(context, Wcp, bcp, nullptr, bufC, MC, CC, DC, 0);

    for (int l = 0; l < LL; l++) {
        ln_kernel<<<MQ, 256>>>(bufQ, g1 + l*CC, beta1 + l*CC, bufQN);
        gemm_tf32<<<dim3(CC/128,   MQ/128), blk, smem_gemm>>>(bufQN, Wq  + (size_t)l*CC*CC,   bq  + l*CC,   nullptr, bufQH, MQ, CC,   CC, 0);
        gemm_tf32<<<dim3(2*CC/128, MC/128), blk, smem_gemm>>>(bufC,  Wkv + (size_t)l*CC*2*CC, bkv + l*2*CC, nullptr, bufKV, MC, 2*CC, CC, 0);
        attn_kernel<<<dim3(NQ/64, HH, B_), 256, smem_attn>>>(bufQH, bufKV, cmask, bufO);
        gemm_tf32<<<dim3(CC/128, MQ/128), blk, smem_gemm>>>(bufO, Wo + (size_t)l*CC*CC, bo + l*CC, bufQ, bufQ, MQ, CC, CC, 0);
        ln_kernel<<<MQ, 256>>>(bufQ, g2 + l*CC, beta2 + l*CC, bufQN);
        gemm_tf32<<<dim3(FF/128, MQ/128), blk, smem_gemm>>>(bufQN, W1 + (size_t)l*CC*FF, bf1 + l*FF, nullptr, bufF, MQ, FF, CC, 1);
        gemm_tf32<<<dim3(CC/128, MQ/128), blk, smem_gemm>>>(bufF,  W2 + (size_t)l*FF*CC, bf2 + l*CC, bufQ,    bufQ, MQ, CC, FF, 0);
    }
    ln_kernel<<<MQ, 256>>>(bufQ, gf, betaf, out);
}

// round 3
// speedup vs baseline: 3.6736x; 2.5092x over previous
#include <cuda_runtime.h>
#include <math.h>

#define B_  4
#define NQ  512
#define NC  2048
#define DQ  1024
#define DC  768
#define CC  1024
#define HH  16
#define HD  64
#define LL  2
#define FF  4096
#define EPSLN 1e-5f

// ---------------- scratch (no allocations allowed) ----------------
__device__ float g_bufQ [B_*NQ*CC];
__device__ float g_bufC [B_*NC*CC];
__device__ float g_bufQN[B_*NQ*CC];
__device__ float g_bufQH[B_*NQ*CC];
__device__ float g_bufKV[B_*NC*2*CC];
__device__ float g_bufO [B_*NQ*CC];
__device__ float g_bufF [B_*NQ*FF];

// round fp32 -> tf32 (rna), result kept in fp32 bit-pattern
__device__ __forceinline__ float f2tf(float x) {
    unsigned r;
    asm("cvt.rna.tf32.f32 %0, %1;" : "=r"(r) : "f"(x));
    return __uint_as_float(r);
}

#define MMA_TF32(D, a0,a1,a2,a3, b0,b1)                                          \
    asm volatile(                                                                \
        "mma.sync.aligned.m16n8k8.row.col.f32.tf32.tf32.f32 "                    \
        "{%0,%1,%2,%3}, {%4,%5,%6,%7}, {%8,%9}, {%0,%1,%2,%3};\n"                \
        : "+f"((D)[0]), "+f"((D)[1]), "+f"((D)[2]), "+f"((D)[3])                 \
        : "r"(a0), "r"(a1), "r"(a2), "r"(a3), "r"(b0), "r"(b1))

// ---------------- TF32 tensor-core GEMM (unchanged from R2) ----------------
__global__ __launch_bounds__(256) void gemm_tf32(
    const float* __restrict__ A, const float* __restrict__ W,
    const float* __restrict__ bias, const float* __restrict__ resid,
    float* __restrict__ out, int M, int N, int K, int do_gelu)
{
    extern __shared__ float smx[];
    float* Abuf = smx;          // 2 x 4096
    float* Bbuf = smx + 8192;   // 2 x 4096

    const int tid  = threadIdx.x;
    const int lane = tid & 31;
    const int warp = tid >> 5;
    const int wmi  = warp >> 2;   // 0..1 : m block of 64
    const int wni  = warp & 3;    // 0..3 : n block of 32
    const int lr   = lane >> 2;   // 0..7
    const int lc   = lane & 3;    // 0..3
    const int bm = blockIdx.y * 128;
    const int bn = blockIdx.x * 128;

    const int a_m  = tid >> 3;
    const int a_kq = tid & 7;
    const int b_kq = tid & 7;
    const int b_nq = tid >> 3;

    float4 ra[4];
    float4 rb[4];

    float acc[4][4][4];
    #pragma unroll
    for (int i = 0; i < 4; i++)
        #pragma unroll
        for (int j = 0; j < 4; j++)
            #pragma unroll
            for (int k = 0; k < 4; k++) acc[i][j][k] = 0.f;

    const int ntile = K >> 5;

    {
        const int k0 = 0;
        #pragma unroll
        for (int it = 0; it < 4; it++) {
            int m = a_m + it*32;
            ra[it] = *(const float4*)(A + (size_t)(bm + m) * K + k0 + 4*a_kq);
        }
        #pragma unroll
        for (int j = 0; j < 4; j++)
            rb[j] = *(const float4*)(W + (size_t)(k0 + 4*b_kq + j) * N + bn + 4*b_nq);
        #pragma unroll
        for (int it = 0; it < 4; it++) {
            int m = a_m + it*32;
            int slot = a_kq ^ (m & 7);
            float4 cv = make_float4(f2tf(ra[it].x), f2tf(ra[it].y), f2tf(ra[it].z), f2tf(ra[it].w));
            *(float4*)(Abuf + m*32 + 4*slot) = cv;
        }
        #pragma unroll
        for (int i = 0; i < 4; i++) {
            int n = 4*b_nq + i;
            int slot = b_kq ^ (n & 7);
            const float* r0 = (const float*)&rb[0];
            const float* r1 = (const float*)&rb[1];
            const float* r2 = (const float*)&rb[2];
            const float* r3 = (const float*)&rb[3];
            float4 cv = make_float4(f2tf(r0[i]), f2tf(r1[i]), f2tf(r2[i]), f2tf(r3[i]));
            *(float4*)(Bbuf + n*32 + 4*slot) = cv;
        }
    }
    __syncthreads();

    for (int t = 1; t <= ntile; t++) {
        if (t < ntile) {
            const int k0 = t * 32;
            #pragma unroll
            for (int it = 0; it < 4; it++) {
                int m = a_m + it*32;
                ra[it] = *(const float4*)(A + (size_t)(bm + m) * K + k0 + 4*a_kq);
            }
            #pragma unroll
            for (int j = 0; j < 4; j++)
                rb[j] = *(const float4*)(W + (size_t)(k0 + 4*b_kq + j) * N + bn + 4*b_nq);
        }

        {
            const float* as = Abuf + ((t-1) & 1) * 4096;
            const float* bs = Bbuf + ((t-1) & 1) * 4096;
            #pragma unroll
            for (int kk = 0; kk < 4; kk++) {
                unsigned af[4][4];
                unsigned bf[4][2];
                const int s0 = 4*((2*kk)     ^ lr) + lc;
                const int s1 = 4*((2*kk + 1) ^ lr) + lc;
                #pragma unroll
                for (int fm = 0; fm < 4; fm++) {
                    int m = wmi*64 + fm*16 + lr;
                    const float* p0 = as + m*32;
                    const float* p1 = as + (m + 8)*32;
                    af[fm][0] = __float_as_uint(p0[s0]);
                    af[fm][1] = __float_as_uint(p1[s0]);
                    af[fm][2] = __float_as_uint(p0[s1]);
                    af[fm][3] = __float_as_uint(p1[s1]);
                }
                #pragma unroll
                for (int fn = 0; fn < 4; fn++) {
                    int n = wni*32 + fn*8 + lr;
                    const float* p = bs + n*32;
                    bf[fn][0] = __float_as_uint(p[s0]);
                    bf[fn][1] = __float_as_uint(p[s1]);
                }
                #pragma unroll
                for (int fm = 0; fm < 4; fm++)
                    #pragma unroll
                    for (int fn = 0; fn < 4; fn++)
                        MMA_TF32(acc[fm][fn], af[fm][0], af[fm][1], af[fm][2], af[fm][3],
                                 bf[fn][0], bf[fn][1]);
            }
        }

        if (t < ntile) {
            float* as = Abuf + (t & 1) * 4096;
            float* bs = Bbuf + (t & 1) * 4096;
            #pragma unroll
            for (int it = 0; it < 4; it++) {
                int m = a_m + it*32;
                int slot = a_kq ^ (m & 7);
                float4 cv = make_float4(f2tf(ra[it].x), f2tf(ra[it].y), f2tf(ra[it].z), f2tf(ra[it].w));
                *(float4*)(as + m*32 + 4*slot) = cv;
            }
            #pragma unroll
            for (int i = 0; i < 4; i++) {
                int n = 4*b_nq + i;
                int slot = b_kq ^ (n & 7);
                const float* r0 = (const float*)&rb[0];
                const float* r1 = (const float*)&rb[1];
                const float* r2 = (const float*)&rb[2];
                const float* r3 = (const float*)&rb[3];
                float4 cv = make_float4(f2tf(r0[i]), f2tf(r1[i]), f2tf(r2[i]), f2tf(r3[i]));
                *(float4*)(bs + n*32 + 4*slot) = cv;
            }
            __syncthreads();
        }
    }

    #pragma unroll
    for (int fm = 0; fm < 4; fm++) {
        #pragma unroll
        for (int fn = 0; fn < 4; fn++) {
            int row = bm + wmi*64 + fm*16 + lr;
            int col = bn + wni*32 + fn*8 + 2*lc;
            float2 bv = *(const float2*)(bias + col);

            float v0 = acc[fm][fn][0] + bv.x;
            float v1 = acc[fm][fn][1] + bv.y;
            float v2 = acc[fm][fn][2] + bv.x;
            float v3 = acc[fm][fn][3] + bv.y;
            if (do_gelu) {
                v0 = 0.5f * v0 * (1.f + erff(v0 * 0.70710678118654752f));
                v1 = 0.5f * v1 * (1.f + erff(v1 * 0.70710678118654752f));
                v2 = 0.5f * v2 * (1.f + erff(v2 * 0.70710678118654752f));
                v3 = 0.5f * v3 * (1.f + erff(v3 * 0.70710678118654752f));
            }
            if (resid) {
                float2 r0 = *(const float2*)(resid + (size_t)row * N + col);
                float2 r1 = *(const float2*)(resid + (size_t)(row + 8) * N + col);
                v0 += r0.x; v1 += r0.y; v2 += r1.x; v3 += r1.y;
            }
            *(float2*)(out + (size_t)row * N + col)       = make_float2(v0, v1);
            *(float2*)(out + (size_t)(row + 8) * N + col) = make_float2(v2, v3);
        }
    }
}

// ---------------- LayerNorm (unchanged) ----------------
__global__ __launch_bounds__(256) void ln_kernel(
    const float* __restrict__ x, const float* __restrict__ g,
    const float* __restrict__ b, float* __restrict__ y)
{
    __shared__ float red[256];
    const int row = blockIdx.x;
    const int tid = threadIdx.x;
    const float* xr = x + (size_t)row * CC;

    float v[4];
    float s = 0.f;
    #pragma unroll
    for (int i = 0; i < 4; i++) { v[i] = xr[tid + i*256]; s += v[i]; }
    red[tid] = s; __syncthreads();
    for (int off = 128; off > 0; off >>= 1) {
        if (tid < off) red[tid] += red[tid + off];
        __syncthreads();
    }
    const float mean = red[0] * (1.f / CC);
    __syncthreads();

    float sq = 0.f;
    #pragma unroll
    for (int i = 0; i < 4; i++) { float d = v[i] - mean; sq += d * d; }
    red[tid] = sq; __syncthreads();
    for (int off = 128; off > 0; off >>= 1) {
        if (tid < off) red[tid] += red[tid + off];
        __syncthreads();
    }
    const float rstd = rsqrtf(red[0] * (1.f / CC) + EPSLN);

    #pragma unroll
    for (int i = 0; i < 4; i++) {
        int c = tid + i*256;
        y[(size_t)row * CC + c] = (v[i] - mean) * rstd * g[c] + b[c];
    }
}

// ---------------- tensor-core flash attention (tf32) ----------------
// grid (NQ/64, H, B), 256 threads = 8 warps: warp = (wq 0..3, wk 0..1).
// wq: 16 q-rows; wk: 32-key half (S phase) / 32-d half (PV phase).
#define AP 68
__global__ __launch_bounds__(256) void attn_tc(
    const float* __restrict__ QH, const float* __restrict__ KV,
    const int* __restrict__ mask, float* __restrict__ OUT)
{
    extern __shared__ float sm[];
    float* Qs = sm;              // 64 x 68   [q][d]   (pre-scaled, tf32)
    float* Ks = Qs + 64*AP;      // 64 x 68   [key][d]
    float* Vs = Ks + 64*AP;      // 64 x 68   [d][key] (transposed)
    float* Ps = Vs + 64*AP;      // 64 x 68   [q][key]
    float* Mv = Ps + 64*AP;      // 64        additive mask (0 / -1e30)
    float* hm = Mv + 64;         // 2 x 64    per-half row max
    float* hs = hm + 128;        // 2 x 64    per-half row sum

    const int tid  = threadIdx.x;
    const int lane = tid & 31;
    const int warp = tid >> 5;
    const int wq   = warp >> 1;
    const int wk   = warp & 1;
    const int lr   = lane >> 2;
    const int lc   = lane & 3;
    const int b = blockIdx.z, h = blockIdx.y;
    const int q0 = blockIdx.x * 64;

    // stage Q once (scaled by HD^-0.5, tf32)
    {
        int r  = tid >> 2;
        int j0 = tid & 3;
        const float4* src = (const float4*)(QH + (size_t)(b*NQ + q0 + r)*CC + h*HD);
        #pragma unroll
        for (int i = 0; i < 4; i++) {
            int j = j0 + 4*i;
            float4 v = src[j];
            float* d = Qs + r*AP + 4*j;
            d[0] = f2tf(0.125f * v.x);
            d[1] = f2tf(0.125f * v.y);
            d[2] = f2tf(0.125f * v.z);
            d[3] = f2tf(0.125f * v.w);
        }
    }

    const int row0 = 16*wq + lr;
    const int row1 = row0 + 8;

    float m0 = -1e30f, m1 = -1e30f, l0 = 0.f, l1 = 0.f;
    float oacc[4][4];
    #pragma unroll
    for (int fn = 0; fn < 4; fn++)
        #pragma unroll
        for (int r = 0; r < 4; r++) oacc[fn][r] = 0.f;

    for (int kc = 0; kc < NC; kc += 64) {
        __syncthreads();   // previous chunk's MMAs done reading Ks/Vs/Mv

        // stage K [key][d], V transposed [d][key], mask
        {
            int r  = tid >> 2;      // key row 0..63
            int j0 = tid & 3;
            const float4* srcK = (const float4*)(KV + (size_t)(b*NC + kc + r)*(2*CC) + h*HD);
            const float4* srcV = (const float4*)(KV + (size_t)(b*NC + kc + r)*(2*CC) + CC + h*HD);
            #pragma unroll
            for (int i = 0; i < 4; i++) {
                int j = j0 + 4*i;
                float4 kv4 = srcK[j];
                float* dk = Ks + r*AP + 4*j;
                dk[0] = f2tf(kv4.x); dk[1] = f2tf(kv4.y);
                dk[2] = f2tf(kv4.z); dk[3] = f2tf(kv4.w);
                float4 vv4 = srcV[j];
                Vs[(4*j + 0)*AP + r] = f2tf(vv4.x);
                Vs[(4*j + 1)*AP + r] = f2tf(vv4.y);
                Vs[(4*j + 2)*AP + r] = f2tf(vv4.z);
                Vs[(4*j + 3)*AP + r] = f2tf(vv4.w);
            }
            if (tid < 64)
                Mv[tid] = (mask[b*NC + kc + tid] != 0) ? 0.f : -1e30f;
        }
        __syncthreads();

        // ---- S = Q @ K^T for this warp: rows 16*wq.., keys 32*wk.. ----
        float sfr[4][4];
        #pragma unroll
        for (int fn = 0; fn < 4; fn++)
            #pragma unroll
            for (int r = 0; r < 4; r++) sfr[fn][r] = 0.f;

        {
            const float* aQ = Qs + row0*AP;
            #pragma unroll
            for (int ks = 0; ks < 8; ks++) {
                int k0 = 8*ks + lc;
                unsigned a0 = __float_as_uint(aQ[k0]);
                unsigned a1 = __float_as_uint(aQ[8*AP + k0]);
                unsigned a2 = __float_as_uint(aQ[k0 + 4]);
                unsigned a3 = __float_as_uint(aQ[8*AP + k0 + 4]);
                #pragma unroll
                for (int fn = 0; fn < 4; fn++) {
                    const float* bK = Ks + (32*wk + 8*fn + lr)*AP;
                    unsigned b0 = __float_as_uint(bK[k0]);
                    unsigned b1 = __float_as_uint(bK[k0 + 4]);
                    MMA_TF32(sfr[fn], a0, a1, a2, a3, b0, b1);
                }
            }
        }

        // ---- mask + row max ----
        float mx0 = -1e30f, mx1 = -1e30f;
        float mc0[4], mc1[4];
        #pragma unroll
        for (int fn = 0; fn < 4; fn++) {
            int col = 32*wk + 8*fn + 2*lc;
            mc0[fn] = Mv[col];
            mc1[fn] = Mv[col + 1];
            sfr[fn][0] += mc0[fn]; sfr[fn][1] += mc1[fn];
            sfr[fn][2] += mc0[fn]; sfr[fn][3] += mc1[fn];
            mx0 = fmaxf(mx0, fmaxf(sfr[fn][0], sfr[fn][1]));
            mx1 = fmaxf(mx1, fmaxf(sfr[fn][2], sfr[fn][3]));
        }
        mx0 = fmaxf(mx0, __shfl_xor_sync(0xffffffffu, mx0, 1));
        mx0 = fmaxf(mx0, __shfl_xor_sync(0xffffffffu, mx0, 2));
        mx1 = fmaxf(mx1, __shfl_xor_sync(0xffffffffu, mx1, 1));
        mx1 = fmaxf(mx1, __shfl_xor_sync(0xffffffffu, mx1, 2));
        if (lc == 0) {
            hm[wk*64 + row0] = mx0;
            hm[wk*64 + row1] = mx1;
        }
        __syncthreads();

        const float nm0 = fmaxf(m0, fmaxf(hm[row0], hm[64 + row0]));
        const float nm1 = fmaxf(m1, fmaxf(hm[row1], hm[64 + row1]));
        const float al0 = __expf(m0 - nm0);
        const float al1 = __expf(m1 - nm1);

        // ---- p = exp(s - m) * maskbit, write Ps, partial row sums ----
        float sum0 = 0.f, sum1 = 0.f;
        #pragma unroll
        for (int fn = 0; fn < 4; fn++) {
            float mb0 = (mc0[fn] == 0.f) ? 1.f : 0.f;
            float mb1 = (mc1[fn] == 0.f) ? 1.f : 0.f;
            float p0 = __expf(sfr[fn][0] - nm0) * mb0;
            float p1 = __expf(sfr[fn][1] - nm0) * mb1;
            float p2 = __expf(sfr[fn][2] - nm1) * mb0;
            float p3 = __expf(sfr[fn][3] - nm1) * mb1;
            sum0 += p0 + p1;
            sum1 += p2 + p3;
            int col = 32*wk + 8*fn + 2*lc;
            *(float2*)(Ps + row0*AP + col) = make_float2(f2tf(p0), f2tf(p1));
            *(float2*)(Ps + row1*AP + col) = make_float2(f2tf(p2), f2tf(p3));
        }
        sum0 += __shfl_xor_sync(0xffffffffu, sum0, 1);
        sum0 += __shfl_xor_sync(0xffffffffu, sum0, 2);
        sum1 += __shfl_xor_sync(0xffffffffu, sum1, 1);
        sum1 += __shfl_xor_sync(0xffffffffu, sum1, 2);
        if (lc == 0) {
            hs[wk*64 + row0] = sum0;
            hs[wk*64 + row1] = sum1;
        }

        // rescale running accumulators
        #pragma unroll
        for (int fn = 0; fn < 4; fn++) {
            oacc[fn][0] *= al0; oacc[fn][1] *= al0;
            oacc[fn][2] *= al1; oacc[fn][3] *= al1;
        }
        __syncthreads();

        l0 = l0 * al0 + hs[row0] + hs[64 + row0];
        l1 = l1 * al1 + hs[row1] + hs[64 + row1];
        m0 = nm0; m1 = nm1;

        // ---- O += P @ V : rows 16*wq.., d = 32*wk.. ----
        {
            const float* aP = Ps + row0*AP;
            #pragma unroll
            for (int ks = 0; ks < 8; ks++) {
                int k0 = 8*ks + lc;
                unsigned a0 = __float_as_uint(aP[k0]);
                unsigned a1 = __float_as_uint(aP[8*AP + k0]);
                unsigned a2 = __float_as_uint(aP[k0 + 4]);
                unsigned a3 = __float_as_uint(aP[8*AP + k0 + 4]);
                #pragma unroll
                for (int fn = 0; fn < 4; fn++) {
                    const float* bV = Vs + (32*wk + 8*fn + lr)*AP;
                    unsigned b0 = __float_as_uint(bV[k0]);
                    unsigned b1 = __float_as_uint(bV[k0 + 4]);
                    MMA_TF32(oacc[fn], a0, a1, a2, a3, b0, b1);
                }
            }
        }
    }

    // ---- normalize + write out ----
    const float il0 = 1.f / l0;
    const float il1 = 1.f / l1;
    #pragma unroll
    for (int fn = 0; fn < 4; fn++) {
        int col = h*HD + 32*wk + 8*fn + 2*lc;
        *(float2*)(OUT + (size_t)(b*NQ + q0 + row0)*CC + col) =
            make_float2(oacc[fn][0]*il0, oacc[fn][1]*il0);
        *(float2*)(OUT + (size_t)(b*NQ + q0 + row1)*CC + col) =
            make_float2(oacc[fn][2]*il1, oacc[fn][3]*il1);
    }
}

// ---------------- orchestration ----------------
extern "C" void kernel_launch(void* const* d_in, const int* in_sizes, int n_in,
                              void* d_out, int out_size)
{
    const float* query   = (const float*)d_in[0];
    const float* context = (const float*)d_in[1];
    const int*   cmask   = (const int*)  d_in[2];
    const float* Wqp   = (const float*)d_in[3];
    const float* bqp   = (const float*)d_in[4];
    const float* Wcp   = (const float*)d_in[5];
    const float* bcp   = (const float*)d_in[6];
    const float* Wq    = (const float*)d_in[7];
    const float* bq    = (const float*)d_in[8];
    const float* Wkv   = (const float*)d_in[9];
    const float* bkv   = (const float*)d_in[10];
    const float* Wo    = (const float*)d_in[11];
    const float* bo    = (const float*)d_in[12];
    const float* g1    = (const float*)d_in[13];
    const float* beta1 = (const float*)d_in[14];
    const float* W1    = (const float*)d_in[15];
    const float* bf1   = (const float*)d_in[16];
    const float* W2    = (const float*)d_in[17];
    const float* bf2   = (const float*)d_in[18];
    const float* g2    = (const float*)d_in[19];
    const float* beta2 = (const float*)d_in[20];
    const float* gf    = (const float*)d_in[21];
    const float* betaf = (const float*)d_in[22];
    float* out = (float*)d_out;

    float *bufQ, *bufC, *bufQN, *bufQH, *bufKV, *bufO, *bufF;
    cudaGetSymbolAddress((void**)&bufQ,  g_bufQ);
    cudaGetSymbolAddress((void**)&bufC,  g_bufC);
    cudaGetSymbolAddress((void**)&bufQN, g_bufQN);
    cudaGetSymbolAddress((void**)&bufQH, g_bufQH);
    cudaGetSymbolAddress((void**)&bufKV, g_bufKV);
    cudaGetSymbolAddress((void**)&bufO,  g_bufO);
    cudaGetSymbolAddress((void**)&bufF,  g_bufF);

    const int smem_gemm = 16384 * (int)sizeof(float);             // 64 KB
    cudaFuncSetAttribute(gemm_tf32, cudaFuncAttributeMaxDynamicSharedMemorySize, smem_gemm);
    const int smem_attn = (4*64*AP + 64 + 128 + 128) * (int)sizeof(float);  // ~70.9 KB
    cudaFuncSetAttribute(attn_tc, cudaFuncAttributeMaxDynamicSharedMemorySize, smem_attn);

    const dim3 blk(256);
    const int MQ = B_ * NQ;   // 2048
    const int MC = B_ * NC;   // 8192

    gemm_tf32<<<dim3(CC/128, MQ/128), blk, smem_gemm>>>(query,   Wqp, bqp, nullptr, bufQ, MQ, CC, DQ, 0);
    gemm_tf32<<<dim3(CC/128, MC/128), blk, smem_gemm>>>(context, Wcp, bcp, nullptr, bufC, MC, CC, DC, 0);

    for (int l = 0; l < LL; l++) {
        ln_kernel<<<MQ, 256>>>(bufQ, g1 + l*CC, beta1 + l*CC, bufQN);
        gemm_tf32<<<dim3(CC/128,   MQ/128), blk, smem_gemm>>>(bufQN, Wq  + (size_t)l*CC*CC,   bq  + l*CC,   nullptr, bufQH, MQ, CC,   CC, 0);
        gemm_tf32<<<dim3(2*CC/128, MC/128), blk, smem_gemm>>>(bufC,  Wkv + (size_t)l*CC*2*CC, bkv + l*2*CC, nullptr, bufKV, MC, 2*CC, CC, 0);
        attn_tc<<<dim3(NQ/64, HH, B_), blk, smem_attn>>>(bufQH, bufKV, cmask, bufO);
        gemm_tf32<<<dim3(CC/128, MQ/128), blk, smem_gemm>>>(bufO, Wo + (size_t)l*CC*CC, bo + l*CC, bufQ, bufQ, MQ, CC, CC, 0);
        ln_kernel<<<MQ, 256>>>(bufQ, g2 + l*CC, beta2 + l*CC, bufQN);
        gemm_tf32<<<dim3(FF/128, MQ/128), blk, smem_gemm>>>(bufQN, W1 + (size_t)l*CC*FF, bf1 + l*FF, nullptr, bufF, MQ, FF, CC, 1);
        gemm_tf32<<<dim3(CC/128, MQ/128), blk, smem_gemm>>>(bufF,  W2 + (size_t)l*FF*CC, bf2 + l*CC, bufQ,    bufQ, MQ, CC, FF, 0);
    }
    ln_kernel<<<MQ, 256>>>(bufQ, gf, betaf, out);
}

// round 5
// speedup vs baseline: 4.8429x; 1.3183x over previous
#include <cuda_runtime.h>
#include <math.h>

#define B_  4
#define NQ  512
#define NC  2048
#define DQ  1024
#define DC  768
#define CC  1024
#define HH  16
#define HD  64
#define LL  2
#define FF  4096
#define EPSLN 1e-5f

// ---------------- scratch (no allocations allowed) ----------------
__device__ float g_bufQ [B_*NQ*CC];
__device__ float g_bufC [B_*NC*CC];
__device__ float g_bufQN[B_*NQ*CC];
__device__ float g_bufQH[B_*NQ*CC];
__device__ float g_bufKV[B_*NC*2*CC];
__device__ float g_bufO [B_*NQ*CC];
__device__ float g_bufF [B_*NQ*FF];
// tf32-rounded copies of GEMM operands
__device__ float g_rQuery[B_*NQ*DQ];
__device__ float g_rCtx  [B_*NC*DC];
__device__ float g_rWqp  [DQ*CC];
__device__ float g_rWcp  [DC*CC];
__device__ float g_rWq   [LL*CC*CC];
__device__ float g_rWkv  [LL*CC*2*CC];
__device__ float g_rWo   [LL*CC*CC];
__device__ float g_rW1   [LL*CC*FF];
__device__ float g_rW2   [LL*FF*CC];

__device__ __forceinline__ float f2tf(float x) {
    unsigned r;
    asm("cvt.rna.tf32.f32 %0, %1;" : "=r"(r) : "f"(x));
    return __uint_as_float(r);
}

#define MMA_TF32(D, a0,a1,a2,a3, b0,b1)                                          \
    asm volatile(                                                                \
        "mma.sync.aligned.m16n8k8.row.col.f32.tf32.tf32.f32 "                    \
        "{%0,%1,%2,%3}, {%4,%5,%6,%7}, {%8,%9}, {%0,%1,%2,%3};\n"                \
        : "+f"((D)[0]), "+f"((D)[1]), "+f"((D)[2]), "+f"((D)[3])                 \
        : "r"(a0), "r"(a1), "r"(a2), "r"(a3), "r"(b0), "r"(b1))

__device__ __forceinline__ void cp16(unsigned dst, const float* src) {
    asm volatile("cp.async.cg.shared.global [%0], [%1], 16;" :: "r"(dst), "l"(src));
}
__device__ __forceinline__ void cpcommit() { asm volatile("cp.async.commit_group;"); }
__device__ __forceinline__ void cpwait0()  { asm volatile("cp.async.wait_group 0;"); }
__device__ __forceinline__ void cpwait1()  { asm volatile("cp.async.wait_group 1;"); }

// ---------------- roundcopy: dst = tf32_rna(src) ----------------
__global__ __launch_bounds__(256) void roundcopy(
    const float* __restrict__ src, float* __restrict__ dst, int n)
{
    int i = (blockIdx.x * 256 + threadIdx.x) * 4;
    if (i < n) {
        float4 v = *(const float4*)(src + i);
        v.x = f2tf(v.x); v.y = f2tf(v.y); v.z = f2tf(v.z); v.w = f2tf(v.w);
        *(float4*)(dst + i) = v;
    }
}

// ---------------- TF32 tensor-core GEMM v2: cp.async pipeline ----------------
// out[M,N] = A[M,K] @ W[K,N] + bias (+gelu) (+resid) (+round)
// A,W must be pre-rounded to tf32. 128x128 tile, BK=32, 256 thr, 2 CTAs/SM.
// flags: 1 = gelu, 2 = round output to tf32.
__global__ __launch_bounds__(256, 2) void gemm_tf32(
    const float* __restrict__ A, const float* __restrict__ W,
    const float* __restrict__ bias, const float* __restrict__ resid,
    float* __restrict__ out, int M, int N, int K, int flags)
{
    extern __shared__ float smx[];  // buf0: A[0..4095] B[4096..8191]; buf1: +8192
    const int tid  = threadIdx.x;
    const int lane = tid & 31;
    const int warp = tid >> 5;
    const int wmi  = warp >> 2;
    const int wni  = warp & 3;
    const int lr   = lane >> 2;
    const int lc   = lane & 3;
    const int bm = blockIdx.y * 128;
    const int bn = blockIdx.x * 128;

    const int sa_m  = tid >> 1;
    const int sa_k4 = (tid & 1) * 4;
    const int sb_k  = tid >> 3;
    const int sb_g4 = (tid & 7) * 4;

    unsigned sbase = (unsigned)__cvta_generic_to_shared(smx);
    unsigned a_dst[4], b_dst[4];
    #pragma unroll
    for (int i = 0; i < 4; i++) {
        int kq = sa_k4 + i;
        a_dst[i] = sbase + (sa_m*32 + 4*(kq ^ (sa_m & 7))) * 4u;
        int ng = sb_g4 + i;
        b_dst[i] = sbase + 16384u + (sb_k*128 + 4*(ng ^ ((sb_k & 3) << 1))) * 4u;
    }
    const float* aSrc = A + (size_t)(bm + sa_m) * K + 4*sa_k4;
    const float* bSrc = W + (size_t)sb_k * N + bn + 4*sb_g4;

    float acc[4][4][4];
    #pragma unroll
    for (int i = 0; i < 4; i++)
        #pragma unroll
        for (int j = 0; j < 4; j++)
            #pragma unroll
            for (int k = 0; k < 4; k++) acc[i][j][k] = 0.f;

    const int ntile = K >> 5;

    // stage(t) helper inlined
    #define STAGE(t) do {                                                        \
        unsigned boff = ((t) & 1) * 32768u;                                      \
        const float* sa = aSrc + (t) * 32;                                       \
        const float* sb = bSrc + (size_t)(t) * 32 * N;                           \
        _Pragma("unroll")                                                        \
        for (int i = 0; i < 4; i++) {                                            \
            cp16(a_dst[i] + boff, sa + 4*i);                                     \
            cp16(b_dst[i] + boff, sb + 4*i);                                     \
        }                                                                        \
        cpcommit();                                                              \
    } while (0)

    STAGE(0);
    STAGE(1);

    const int cgb  = wni*8 + (lr >> 2);
    const int lce  = lr & 3;
    const int lcx2 = lc << 1;

    for (int t = 0; t < ntile; t++) {
        if (t + 1 < ntile) cpwait1(); else cpwait0();
        __syncthreads();

        const float* as = smx + (t & 1) * 8192;
        const float* bs = as + 4096;
        const float* aw = as + (wmi*64 + lr) * 32;

        #pragma unroll
        for (int kk = 0; kk < 4; kk++) {
            const int s0 = 4*((2*kk)     ^ lr) + lc;
            const int s1 = 4*((2*kk + 1) ^ lr) + lc;
            unsigned af[4][4], bf[4][2];
            #pragma unroll
            for (int fm = 0; fm < 4; fm++) {
                const float* p0 = aw + fm*512;
                af[fm][0] = __float_as_uint(p0[s0]);
                af[fm][1] = __float_as_uint(p0[256 + s0]);
                af[fm][2] = __float_as_uint(p0[s1]);
                af[fm][3] = __float_as_uint(p0[256 + s1]);
            }
            const float* bk = bs + (8*kk + lc) * 128;
            #pragma unroll
            for (int fn = 0; fn < 4; fn++) {
                int off = 4*((cgb + fn*2) ^ lcx2) + lce;
                bf[fn][0] = __float_as_uint(bk[off]);
                bf[fn][1] = __float_as_uint(bk[512 + off]);
            }
            #pragma unroll
            for (int fm = 0; fm < 4; fm++)
                #pragma unroll
                for (int fn = 0; fn < 4; fn++)
                    MMA_TF32(acc[fm][fn], af[fm][0], af[fm][1], af[fm][2], af[fm][3],
                             bf[fn][0], bf[fn][1]);
        }
        __syncthreads();
        if (t + 2 < ntile) STAGE(t + 2);
    }
    #undef STAGE

    // ---- epilogue ----
    const int do_gelu  = flags & 1;
    const int do_round = flags & 2;
    #pragma unroll
    for (int fm = 0; fm < 4; fm++) {
        #pragma unroll
        for (int fn = 0; fn < 4; fn++) {
            int row = bm + wmi*64 + fm*16 + lr;
            int col = bn + wni*32 + fn*8 + 2*lc;
            float2 bv = *(const float2*)(bias + col);

            float v0 = acc[fm][fn][0] + bv.x;
            float v1 = acc[fm][fn][1] + bv.y;
            float v2 = acc[fm][fn][2] + bv.x;
            float v3 = acc[fm][fn][3] + bv.y;
            if (do_gelu) {
                v0 = 0.5f * v0 * (1.f + erff(v0 * 0.70710678118654752f));
                v1 = 0.5f * v1 * (1.f + erff(v1 * 0.70710678118654752f));
                v2 = 0.5f * v2 * (1.f + erff(v2 * 0.70710678118654752f));
                v3 = 0.5f * v3 * (1.f + erff(v3 * 0.70710678118654752f));
            }
            if (resid) {
                float2 r0 = *(const float2*)(resid + (size_t)row * N + col);
                float2 r1 = *(const float2*)(resid + (size_t)(row + 8) * N + col);
                v0 += r0.x; v1 += r0.y; v2 += r1.x; v3 += r1.y;
            }
            if (do_round) {
                v0 = f2tf(v0); v1 = f2tf(v1); v2 = f2tf(v2); v3 = f2tf(v3);
            }
            *(float2*)(out + (size_t)row * N + col)       = make_float2(v0, v1);
            *(float2*)(out + (size_t)(row + 8) * N + col) = make_float2(v2, v3);
        }
    }
}

// ---------------- LayerNorm (optional tf32-round of output) ----------------
__global__ __launch_bounds__(256) void ln_kernel(
    const float* __restrict__ x, const float* __restrict__ g,
    const float* __restrict__ b, float* __restrict__ y, int do_round)
{
    __shared__ float red[256];
    const int row = blockIdx.x;
    const int tid = threadIdx.x;
    const float* xr = x + (size_t)row * CC;

    float v[4];
    float s = 0.f;
    #pragma unroll
    for (int i = 0; i < 4; i++) { v[i] = xr[tid + i*256]; s += v[i]; }
    red[tid] = s; __syncthreads();
    for (int off = 128; off > 0; off >>= 1) {
        if (tid < off) red[tid] += red[tid + off];
        __syncthreads();
    }
    const float mean = red[0] * (1.f / CC);
    __syncthreads();

    float sq = 0.f;
    #pragma unroll
    for (int i = 0; i < 4; i++) { float d = v[i] - mean; sq += d * d; }
    red[tid] = sq; __syncthreads();
    for (int off = 128; off > 0; off >>= 1) {
        if (tid < off) red[tid] += red[tid + off];
        __syncthreads();
    }
    const float rstd = rsqrtf(red[0] * (1.f / CC) + EPSLN);

    #pragma unroll
    for (int i = 0; i < 4; i++) {
        int c = tid + i*256;
        float o = (v[i] - mean) * rstd * g[c] + b[c];
        y[(size_t)row * CC + c] = do_round ? f2tf(o) : o;
    }
}

// ---------------- tensor-core flash attention (tf32, pre-rounded inputs) ----------------
#define AP 68
__global__ __launch_bounds__(256) void attn_tc(
    const float* __restrict__ QH, const float* __restrict__ KV,
    const int* __restrict__ mask, float* __restrict__ OUT)
{
    extern __shared__ float sm[];
    float* Qs = sm;
    float* Ks = Qs + 64*AP;
    float* Vs = Ks + 64*AP;
    float* Ps = Vs + 64*AP;
    float* Mv = Ps + 64*AP;
    float* hm = Mv + 64;
    float* hs = hm + 128;

    const int tid  = threadIdx.x;
    const int lane = tid & 31;
    const int warp = tid >> 5;
    const int wq   = warp >> 1;
    const int wk   = warp & 1;
    const int lr   = lane >> 2;
    const int lc   = lane & 3;
    const int b = blockIdx.z, h = blockIdx.y;
    const int q0 = blockIdx.x * 64;

    {
        int r  = tid >> 2;
        int j0 = tid & 3;
        const float4* src = (const float4*)(QH + (size_t)(b*NQ + q0 + r)*CC + h*HD);
        #pragma unroll
        for (int i = 0; i < 4; i++) {
            int j = j0 + 4*i;
            float4 v = src[j];
            float* d = Qs + r*AP + 4*j;
            d[0] = 0.125f * v.x; d[1] = 0.125f * v.y;
            d[2] = 0.125f * v.z; d[3] = 0.125f * v.w;
        }
    }

    const int row0 = 16*wq + lr;
    const int row1 = row0 + 8;

    float m0 = -1e30f, m1 = -1e30f, l0 = 0.f, l1 = 0.f;
    float oacc[4][4];
    #pragma unroll
    for (int fn = 0; fn < 4; fn++)
        #pragma unroll
        for (int r = 0; r < 4; r++) oacc[fn][r] = 0.f;

    for (int kc = 0; kc < NC; kc += 64) {
        __syncthreads();

        {
            int r  = tid >> 2;
            int j0 = tid & 3;
            const float4* srcK = (const float4*)(KV + (size_t)(b*NC + kc + r)*(2*CC) + h*HD);
            const float4* srcV = (const float4*)(KV + (size_t)(b*NC + kc + r)*(2*CC) + CC + h*HD);
            #pragma unroll
            for (int i = 0; i < 4; i++) {
                int j = j0 + 4*i;
                float4 kv4 = srcK[j];
                float* dk = Ks + r*AP + 4*j;
                dk[0] = kv4.x; dk[1] = kv4.y; dk[2] = kv4.z; dk[3] = kv4.w;
                float4 vv4 = srcV[j];
                Vs[(4*j + 0)*AP + r] = vv4.x;
                Vs[(4*j + 1)*AP + r] = vv4.y;
                Vs[(4*j + 2)*AP + r] = vv4.z;
                Vs[(4*j + 3)*AP + r] = vv4.w;
            }
            if (tid < 64)
                Mv[tid] = (mask[b*NC + kc + tid] != 0) ? 0.f : -1e30f;
        }
        __syncthreads();

        float sfr[4][4];
        #pragma unroll
        for (int fn = 0; fn < 4; fn++)
            #pragma unroll
            for (int r = 0; r < 4; r++) sfr[fn][r] = 0.f;

        {
            const float* aQ = Qs + row0*AP;
            #pragma unroll
            for (int ks = 0; ks < 8; ks++) {
                int k0 = 8*ks + lc;
                unsigned a0 = __float_as_uint(aQ[k0]);
                unsigned a1 = __float_as_uint(aQ[8*AP + k0]);
                unsigned a2 = __float_as_uint(aQ[k0 + 4]);
                unsigned a3 = __float_as_uint(aQ[8*AP + k0 + 4]);
                #pragma unroll
                for (int fn = 0; fn < 4; fn++) {
                    const float* bK = Ks + (32*wk + 8*fn + lr)*AP;
                    unsigned b0 = __float_as_uint(bK[k0]);
                    unsigned b1 = __float_as_uint(bK[k0 + 4]);
                    MMA_TF32(sfr[fn], a0, a1, a2, a3, b0, b1);
                }
            }
        }

        float mx0 = -1e30f, mx1 = -1e30f;
        float mc0[4], mc1[4];
        #pragma unroll
        for (int fn = 0; fn < 4; fn++) {
            int col = 32*wk + 8*fn + 2*lc;
            mc0[fn] = Mv[col];
            mc1[fn] = Mv[col + 1];
            sfr[fn][0] += mc0[fn]; sfr[fn][1] += mc1[fn];
            sfr[fn][2] += mc0[fn]; sfr[fn][3] += mc1[fn];
            mx0 = fmaxf(mx0, fmaxf(sfr[fn][0], sfr[fn][1]));
            mx1 = fmaxf(mx1, fmaxf(sfr[fn][2], sfr[fn][3]));
        }
        mx0 = fmaxf(mx0, __shfl_xor_sync(0xffffffffu, mx0, 1));
        mx0 = fmaxf(mx0, __shfl_xor_sync(0xffffffffu, mx0, 2));
        mx1 = fmaxf(mx1, __shfl_xor_sync(0xffffffffu, mx1, 1));
        mx1 = fmaxf(mx1, __shfl_xor_sync(0xffffffffu, mx1, 2));
        if (lc == 0) {
            hm[wk*64 + row0] = mx0;
            hm[wk*64 + row1] = mx1;
        }
        __syncthreads();

        const float nm0 = fmaxf(m0, fmaxf(hm[row0], hm[64 + row0]));
        const float nm1 = fmaxf(m1, fmaxf(hm[row1], hm[64 + row1]));
        const float al0 = __expf(m0 - nm0);
        const float al1 = __expf(m1 - nm1);

        float sum0 = 0.f, sum1 = 0.f;
        #pragma unroll
        for (int fn = 0; fn < 4; fn++) {
            float mb0 = (mc0[fn] == 0.f) ? 1.f : 0.f;
            float mb1 = (mc1[fn] == 0.f) ? 1.f : 0.f;
            float p0 = __expf(sfr[fn][0] - nm0) * mb0;
            float p1 = __expf(sfr[fn][1] - nm0) * mb1;
            float p2 = __expf(sfr[fn][2] - nm1) * mb0;
            float p3 = __expf(sfr[fn][3] - nm1) * mb1;
            sum0 += p0 + p1;
            sum1 += p2 + p3;
            int col = 32*wk + 8*fn + 2*lc;
            *(float2*)(Ps + row0*AP + col) = make_float2(f2tf(p0), f2tf(p1));
            *(float2*)(Ps + row1*AP + col) = make_float2(f2tf(p2), f2tf(p3));
        }
        sum0 += __shfl_xor_sync(0xffffffffu, sum0, 1);
        sum0 += __shfl_xor_sync(0xffffffffu, sum0, 2);
        sum1 += __shfl_xor_sync(0xffffffffu, sum1, 1);
        sum1 += __shfl_xor_sync(0xffffffffu, sum1, 2);
        if (lc == 0) {
            hs[wk*64 + row0] = sum0;
            hs[wk*64 + row1] = sum1;
        }

        #pragma unroll
        for (int fn = 0; fn < 4; fn++) {
            oacc[fn][0] *= al0; oacc[fn][1] *= al0;
            oacc[fn][2] *= al1; oacc[fn][3] *= al1;
        }
        __syncthreads();

        l0 = l0 * al0 + hs[row0] + hs[64 + row0];
        l1 = l1 * al1 + hs[row1] + hs[64 + row1];
        m0 = nm0; m1 = nm1;

        {
            const float* aP = Ps + row0*AP;
            #pragma unroll
            for (int ks = 0; ks < 8; ks++) {
                int k0 = 8*ks + lc;
                unsigned a0 = __float_as_uint(aP[k0]);
                unsigned a1 = __float_as_uint(aP[8*AP + k0]);
                unsigned a2 = __float_as_uint(aP[k0 + 4]);
                unsigned a3 = __float_as_uint(aP[8*AP + k0 + 4]);
                #pragma unroll
                for (int fn = 0; fn < 4; fn++) {
                    const float* bV = Vs + (32*wk + 8*fn + lr)*AP;
                    unsigned b0 = __float_as_uint(bV[k0]);
                    unsigned b1 = __float_as_uint(bV[k0 + 4]);
                    MMA_TF32(oacc[fn], a0, a1, a2, a3, b0, b1);
                }
            }
        }
    }

    const float il0 = 1.f / l0;
    const float il1 = 1.f / l1;
    #pragma unroll
    for (int fn = 0; fn < 4; fn++) {
        int col = h*HD + 32*wk + 8*fn + 2*lc;
        *(float2*)(OUT + (size_t)(b*NQ + q0 + row0)*CC + col) =
            make_float2(f2tf(oacc[fn][0]*il0), f2tf(oacc[fn][1]*il0));
        *(float2*)(OUT + (size_t)(b*NQ + q0 + row1)*CC + col) =
            make_float2(f2tf(oacc[fn][2]*il1), f2tf(oacc[fn][3]*il1));
    }
}

// ---------------- orchestration ----------------
extern "C" void kernel_launch(void* const* d_in, const int* in_sizes, int n_in,
                              void* d_out, int out_size)
{
    const float* query   = (const float*)d_in[0];
    const float* context = (const float*)d_in[1];
    const int*   cmask   = (const int*)  d_in[2];
    const float* Wqp   = (const float*)d_in[3];
    const float* bqp   = (const float*)d_in[4];
    const float* Wcp   = (const float*)d_in[5];
    const float* bcp   = (const float*)d_in[6];
    const float* Wq    = (const float*)d_in[7];
    const float* bq    = (const float*)d_in[8];
    const float* Wkv   = (const float*)d_in[9];
    const float* bkv   = (const float*)d_in[10];
    const float* Wo    = (const float*)d_in[11];
    const float* bo    = (const float*)d_in[12];
    const float* g1    = (const float*)d_in[13];
    const float* beta1 = (const float*)d_in[14];
    const float* W1    = (const float*)d_in[15];
    const float* bf1   = (const float*)d_in[16];
    const float* W2    = (const float*)d_in[17];
    const float* bf2   = (const float*)d_in[18];
    const float* g2    = (const float*)d_in[19];
    const float* beta2 = (const float*)d_in[20];
    const float* gf    = (const float*)d_in[21];
    const float* betaf = (const float*)d_in[22];
    float* out = (float*)d_out;

    float *bufQ, *bufC, *bufQN, *bufQH, *bufKV, *bufO, *bufF;
    float *rQuery, *rCtx, *rWqp, *rWcp, *rWq, *rWkv, *rWo, *rW1, *rW2;
    cudaGetSymbolAddress((void**)&bufQ,  g_bufQ);
    cudaGetSymbolAddress((void**)&bufC,  g_bufC);
    cudaGetSymbolAddress((void**)&bufQN, g_bufQN);
    cudaGetSymbolAddress((void**)&bufQH, g_bufQH);
    cudaGetSymbolAddress((void**)&bufKV, g_bufKV);
    cudaGetSymbolAddress((void**)&bufO,  g_bufO);
    cudaGetSymbolAddress((void**)&bufF,  g_bufF);
    cudaGetSymbolAddress((void**)&rQuery, g_rQuery);
    cudaGetSymbolAddress((void**)&rCtx,   g_rCtx);
    cudaGetSymbolAddress((void**)&rWqp,   g_rWqp);
    cudaGetSymbolAddress((void**)&rWcp,   g_rWcp);
    cudaGetSymbolAddress((void**)&rWq,    g_rWq);
    cudaGetSymbolAddress((void**)&rWkv,   g_rWkv);
    cudaGetSymbolAddress((void**)&rWo,    g_rWo);
    cudaGetSymbolAddress((void**)&rW1,    g_rW1);
    cudaGetSymbolAddress((void**)&rW2,    g_rW2);

    const int smem_gemm = 16384 * (int)sizeof(float);             // 64 KB
    cudaFuncSetAttribute(gemm_tf32, cudaFuncAttributeMaxDynamicSharedMemorySize, smem_gemm);
    const int smem_attn = (4*64*AP + 64 + 128 + 128) * (int)sizeof(float);
    cudaFuncSetAttribute(attn_tc, cudaFuncAttributeMaxDynamicSharedMemorySize, smem_attn);

    const dim3 blk(256);
    const int MQ = B_ * NQ;   // 2048
    const int MC = B_ * NC;   // 8192

    // ---- pre-round GEMM operands to tf32 ----
    #define RC(src, dst, n) roundcopy<<<(n)/1024, 256>>>(src, dst, n)
    RC(query,   rQuery, B_*NQ*DQ);
    RC(context, rCtx,   B_*NC*DC);
    RC(Wqp,     rWqp,   DQ*CC);
    RC(Wcp,     rWcp,   DC*CC);
    RC(Wq,      rWq,    LL*CC*CC);
    RC(Wkv,     rWkv,   LL*CC*2*CC);
    RC(Wo,      rWo,    LL*CC*CC);
    RC(W1,      rW1,    LL*CC*FF);
    RC(W2,      rW2,    LL*FF*CC);
    #undef RC

    gemm_tf32<<<dim3(CC/128, MQ/128), blk, smem_gemm>>>(rQuery, rWqp, bqp, nullptr, bufQ, MQ, CC, DQ, 0);
    gemm_tf32<<<dim3(CC/128, MC/128), blk, smem_gemm>>>(rCtx,   rWcp, bcp, nullptr, bufC, MC, CC, DC, 2);

    for (int l = 0; l < LL; l++) {
        ln_kernel<<<MQ, 256>>>(bufQ, g1 + l*CC, beta1 + l*CC, bufQN, 1);
        gemm_tf32<<<dim3(CC/128,   MQ/128), blk, smem_gemm>>>(bufQN, rWq  + (size_t)l*CC*CC,   bq  + l*CC,   nullptr, bufQH, MQ, CC,   CC, 2);
        gemm_tf32<<<dim3(2*CC/128, MC/128), blk, smem_gemm>>>(bufC,  rWkv + (size_t)l*CC*2*CC, bkv + l*2*CC, nullptr, bufKV, MC, 2*CC, CC, 2);
        attn_tc<<<dim3(NQ/64, HH, B_), blk, smem_attn>>>(bufQH, bufKV, cmask, bufO);
        gemm_tf32<<<dim3(CC/128, MQ/128), blk, smem_gemm>>>(bufO, rWo + (size_t)l*CC*CC, bo + l*CC, bufQ, bufQ, MQ, CC, CC, 0);
        ln_kernel<<<MQ, 256>>>(bufQ, g2 + l*CC, beta2 + l*CC, bufQN, 1);
        gemm_tf32<<<dim3(FF/128, MQ/128), blk, smem_gemm>>>(bufQN, rW1 + (size_t)l*CC*FF, bf1 + l*FF, nullptr, bufF, MQ, FF, CC, 3);
        gemm_tf32<<<dim3(CC/128, MQ/128), blk, smem_gemm>>>(bufF,  rW2 + (size_t)l*FF*CC, bf2 + l*CC, bufQ,   bufQ, MQ, CC, FF, 0);
    }
    ln_kernel<<<MQ, 256>>>(bufQ, gf, betaf, out, 0);
}

// round 7
// speedup vs baseline: 8.3393x; 1.7220x over previous
#include <cuda_runtime.h>
#include <cuda_fp16.h>
#include <math.h>
#include <stdint.h>

#define B_  4
#define NQ  512
#define NC  2048
#define DQ  1024
#define DC  768
#define CC  1024
#define HH  16
#define HD  64
#define LL  2
#define FF  4096
#define EPSLN 1e-5f

// ---------------- scratch (no allocations allowed) ----------------
__device__ float  g_bufQ [B_*NQ*CC];        // residual stream (fp32)
__device__ __half g_bufC [B_*NC*CC];
__device__ __half g_bufQN[B_*NQ*CC];
__device__ __half g_bufQH[B_*NQ*CC];
__device__ __half g_bufKV[B_*NC*2*CC];
__device__ __half g_bufO [B_*NQ*CC];
__device__ __half g_bufF [B_*NQ*FF];
// fp16 operands: activations row-major, weights TRANSPOSED [N][K]
__device__ __half g_rQuery[B_*NQ*DQ];
__device__ __half g_rCtx  [B_*NC*DC];
__device__ __half g_rWqp  [DQ*CC];
__device__ __half g_rWcp  [DC*CC];
__device__ __half g_rWq   [LL*CC*CC];
__device__ __half g_rWkv  [LL*CC*2*CC];
__device__ __half g_rWo   [LL*CC*CC];
__device__ __half g_rW1   [LL*CC*FF];
__device__ __half g_rW2   [LL*FF*CC];

#define MMA_F16(D, a0,a1,a2,a3, b0,b1)                                           \
    asm volatile(                                                                \
        "mma.sync.aligned.m16n8k16.row.col.f32.f16.f16.f32 "                     \
        "{%0,%1,%2,%3}, {%4,%5,%6,%7}, {%8,%9}, {%0,%1,%2,%3};\n"                \
        : "+f"((D)[0]), "+f"((D)[1]), "+f"((D)[2]), "+f"((D)[3])                 \
        : "r"(a0), "r"(a1), "r"(a2), "r"(a3), "r"(b0), "r"(b1))

__device__ __forceinline__ void cp16(unsigned dst, const void* src) {
    asm volatile("cp.async.cg.shared.global [%0], [%1], 16;" :: "r"(dst), "l"(src));
}
__device__ __forceinline__ void cpcommit() { asm volatile("cp.async.commit_group;"); }
__device__ __forceinline__ void cpwait0()  { asm volatile("cp.async.wait_group 0;"); }
__device__ __forceinline__ void cpwait1()  { asm volatile("cp.async.wait_group 1;"); }
__device__ __forceinline__ void cpwait2()  { asm volatile("cp.async.wait_group 2;"); }

// ---------------- prep: fp32 -> fp16 ----------------
__global__ __launch_bounds__(256) void tohalf(
    const float* __restrict__ src, __half* __restrict__ dst, int n)
{
    int i = (blockIdx.x * 256 + threadIdx.x) * 4;
    if (i < n) {
        float4 v = *(const float4*)(src + i);
        __half2* d = (__half2*)(dst + i);
        d[0] = __floats2half2_rn(v.x, v.y);
        d[1] = __floats2half2_rn(v.z, v.w);
    }
}

// dst[n][k] = half(src[k][n]); src [K,N] fp32 row-major. grid (N/32, K/32), block (32,8)
__global__ void transpose_half(const float* __restrict__ src, __half* __restrict__ dst,
                               int K, int N)
{
    __shared__ float t[32][33];
    const int n0 = blockIdx.x * 32, k0 = blockIdx.y * 32;
    const int tx = threadIdx.x, ty = threadIdx.y;
    #pragma unroll
    for (int i = 0; i < 4; i++)
        t[ty + 8*i][tx] = src[(size_t)(k0 + ty + 8*i) * N + n0 + tx];
    __syncthreads();
    #pragma unroll
    for (int i = 0; i < 4; i++)
        dst[(size_t)(n0 + ty + 8*i) * K + k0 + tx] = __float2half(t[tx][ty + 8*i]);
}

// ---------------- fp16 tensor-core GEMM, 4-stage cp.async ----------------
// out[M,N] = A[M,K] @ Bt[N,K]^T + bias (+gelu:1) (+resid) ; flags&2 -> half output
// 128x128 tile, BK=32, 256 threads (8 warps 2x4, warp tile 64x32), 2 CTAs/SM.
__global__ __launch_bounds__(256, 2) void gemm_f16(
    const __half* __restrict__ A, const __half* __restrict__ Bt,
    const float* __restrict__ bias, const float* __restrict__ resid,
    void* __restrict__ outv, int M, int N, int K, int flags)
{
    extern __shared__ uint32_t smu[];   // 4 stages x 4096 u32 (A 2048 | B 2048)
    const int tid  = threadIdx.x;
    const int lane = tid & 31;
    const int warp = tid >> 5;
    const int wmi  = warp >> 2;
    const int wni  = warp & 3;
    const int lr   = lane >> 2;
    const int lc   = lane & 3;
    const int bm = blockIdx.y * 128;
    const int bn = blockIdx.x * 128;

    // staging map: thread -> row (0..127), two 16B chunks
    const int srow = tid >> 1;
    const int c0s  = (tid & 1) * 2;
    const int sswz = ((srow >> 1) & 3) << 2;
    const unsigned sbase = (unsigned)__cvta_generic_to_shared(smu);
    unsigned adst[2], bdst[2];
    #pragma unroll
    for (int i = 0; i < 2; i++) {
        int c = c0s + i;
        adst[i] = sbase + (srow*16 + ((4*c) ^ sswz)) * 4u;
        bdst[i] = sbase + 8192u + (srow*16 + ((4*c) ^ sswz)) * 4u;
    }
    const __half* aSrc = A  + (size_t)(bm + srow) * K + 8*c0s;
    const __half* bSrc = Bt + (size_t)(bn + srow) * K + 8*c0s;

    float acc[4][4][4];
    #pragma unroll
    for (int i = 0; i < 4; i++)
        #pragma unroll
        for (int j = 0; j < 4; j++)
            #pragma unroll
            for (int k = 0; k < 4; k++) acc[i][j][k] = 0.f;

    const int T = K >> 5;

    #define STAGE(t) do {                                                        \
        const unsigned boff = ((t) & 3) * 16384u;                                \
        const __half* sa = aSrc + (t) * 32;                                      \
        const __half* sb = bSrc + (t) * 32;                                      \
        cp16(adst[0] + boff, sa);                                                \
        cp16(adst[1] + boff, sa + 8);                                            \
        cp16(bdst[0] + boff, sb);                                                \
        cp16(bdst[1] + boff, sb + 8);                                            \
        cpcommit();                                                              \
    } while (0)

    STAGE(0); STAGE(1); STAGE(2);

    const int fswz = ((lr >> 1) & 3) << 2;   // fragment swizzle, constant per lane
    const int abase0 = (wmi*64 + lr) * 16;
    const int bbase0 = (wni*32 + lr) * 16;

    for (int t = 0; t < T; t++) {
        const int rem = T - 1 - t;
        if (rem >= 2) cpwait2(); else if (rem == 1) cpwait1(); else cpwait0();
        __syncthreads();
        if (t + 3 < T) STAGE(t + 3);

        const uint32_t* as = smu + (t & 3) * 4096;
        const uint32_t* bs = as + 2048;

        #pragma unroll
        for (int t16 = 0; t16 < 2; t16++) {
            const int u0 = (8*t16 + lc) ^ fswz;
            const int u1 = u0 ^ 4;
            uint32_t af[4][4], bf[4][2];
            #pragma unroll
            for (int fm = 0; fm < 4; fm++) {
                const uint32_t* p = as + abase0 + fm*256;   // fm*16 rows * 16 u32
                af[fm][0] = p[u0];
                af[fm][1] = p[128 + u0];
                af[fm][2] = p[u1];
                af[fm][3] = p[128 + u1];
            }
            #pragma unroll
            for (int fn = 0; fn < 4; fn++) {
                const uint32_t* p = bs + bbase0 + fn*128;   // fn*8 rows * 16 u32
                bf[fn][0] = p[u0];
                bf[fn][1] = p[u1];
            }
            #pragma unroll
            for (int fm = 0; fm < 4; fm++)
                #pragma unroll
                for (int fn = 0; fn < 4; fn++)
                    MMA_F16(acc[fm][fn], af[fm][0], af[fm][1], af[fm][2], af[fm][3],
                            bf[fn][0], bf[fn][1]);
        }
    }
    #undef STAGE

    // ---- epilogue ----
    const int do_gelu = flags & 1;
    const int half_out = flags & 2;
    #pragma unroll
    for (int fm = 0; fm < 4; fm++) {
        #pragma unroll
        for (int fn = 0; fn < 4; fn++) {
            int row = bm + wmi*64 + fm*16 + lr;
            int col = bn + wni*32 + fn*8 + 2*lc;
            float2 bv = *(const float2*)(bias + col);

            float v0 = acc[fm][fn][0] + bv.x;
            float v1 = acc[fm][fn][1] + bv.y;
            float v2 = acc[fm][fn][2] + bv.x;
            float v3 = acc[fm][fn][3] + bv.y;
            if (do_gelu) {
                v0 = 0.5f * v0 * (1.f + erff(v0 * 0.70710678118654752f));
                v1 = 0.5f * v1 * (1.f + erff(v1 * 0.70710678118654752f));
                v2 = 0.5f * v2 * (1.f + erff(v2 * 0.70710678118654752f));
                v3 = 0.5f * v3 * (1.f + erff(v3 * 0.70710678118654752f));
            }
            if (resid) {
                float2 r0 = *(const float2*)(resid + (size_t)row * N + col);
                float2 r1 = *(const float2*)(resid + (size_t)(row + 8) * N + col);
                v0 += r0.x; v1 += r0.y; v2 += r1.x; v3 += r1.y;
            }
            if (half_out) {
                __half* o = (__half*)outv;
                *(__half2*)(o + (size_t)row * N + col)       = __floats2half2_rn(v0, v1);
                *(__half2*)(o + (size_t)(row + 8) * N + col) = __floats2half2_rn(v2, v3);
            } else {
                float* o = (float*)outv;
                *(float2*)(o + (size_t)row * N + col)        = make_float2(v0, v1);
                *(float2*)(o + (size_t)(row + 8) * N + col)  = make_float2(v2, v3);
            }
        }
    }
}

// ---------------- LayerNorm: fp32 in, fp32 or fp16 out ----------------
__global__ __launch_bounds__(256) void ln_kernel(
    const float* __restrict__ x, const float* __restrict__ g,
    const float* __restrict__ b, void* __restrict__ yv, int half_out)
{
    __shared__ float red[256];
    const int row = blockIdx.x;
    const int tid = threadIdx.x;
    const float* xr = x + (size_t)row * CC;

    float v[4];
    float s = 0.f;
    #pragma unroll
    for (int i = 0; i < 4; i++) { v[i] = xr[tid + i*256]; s += v[i]; }
    red[tid] = s; __syncthreads();
    for (int off = 128; off > 0; off >>= 1) {
        if (tid < off) red[tid] += red[tid + off];
        __syncthreads();
    }
    const float mean = red[0] * (1.f / CC);
    __syncthreads();

    float sq = 0.f;
    #pragma unroll
    for (int i = 0; i < 4; i++) { float d = v[i] - mean; sq += d * d; }
    red[tid] = sq; __syncthreads();
    for (int off = 128; off > 0; off >>= 1) {
        if (tid < off) red[tid] += red[tid + off];
        __syncthreads();
    }
    const float rstd = rsqrtf(red[0] * (1.f / CC) + EPSLN);

    #pragma unroll
    for (int i = 0; i < 4; i++) {
        int c = tid + i*256;
        float o = (v[i] - mean) * rstd * g[c] + b[c];
        if (half_out) ((__half*)yv)[(size_t)row * CC + c] = __float2half(o);
        else          ((float*)yv)[(size_t)row * CC + c] = o;
    }
}

// ---------------- fp16 tensor-core flash attention ----------------
// grid (NQ/64, H, B), 256 thr = 8 warps (wq 0..3 x wk 0..1). Tiles 64x64 half,
// row stride 36 u32 (72 halves) -> conflict-free fragment LDS.
#define SRH 36
__global__ __launch_bounds__(256) void attn_f16(
    const __half* __restrict__ QH, const __half* __restrict__ KV,
    const int* __restrict__ mask, __half* __restrict__ OUT)
{
    extern __shared__ uint32_t sm32[];
    uint32_t* Qs = sm32;                // 64 x 36
    uint32_t* Ks = Qs + 64*SRH;
    uint32_t* Vs = Ks + 64*SRH;         // [d][key]
    uint32_t* Ps = Vs + 64*SRH;
    float*    Mv = (float*)(Ps + 64*SRH);   // 64
    float*    hm = Mv + 64;                  // 2 x 64
    float*    hs = hm + 128;                 // 2 x 64

    const int tid  = threadIdx.x;
    const int lane = tid & 31;
    const int warp = tid >> 5;
    const int wq   = warp >> 1;
    const int wk   = warp & 1;
    const int lr   = lane >> 2;
    const int lc   = lane & 3;
    const int b = blockIdx.z, h = blockIdx.y;
    const int q0 = blockIdx.x * 64;

    // stage Q once, scaled by 0.125 (exact power-of-2 in fp16)
    {
        const __half2 sc = __float2half2_rn(0.125f);
        int r  = tid >> 2;
        int j0 = tid & 3;
        const uint2* src = (const uint2*)(QH + (size_t)(b*NQ + q0 + r)*CC + h*HD);
        #pragma unroll
        for (int i = 0; i < 4; i++) {
            int j = j0 + 4*i;           // uint2 index, 4 halves each
            uint2 v = src[j];
            __half2 h0 = __hmul2(*(__half2*)&v.x, sc);
            __half2 h1 = __hmul2(*(__half2*)&v.y, sc);
            Qs[r*SRH + 2*j]     = *(uint32_t*)&h0;
            Qs[r*SRH + 2*j + 1] = *(uint32_t*)&h1;
        }
    }

    const int row0 = 16*wq + lr;
    const int row1 = row0 + 8;

    float m0 = -1e30f, m1 = -1e30f, l0 = 0.f, l1 = 0.f;
    float oacc[4][4];
    #pragma unroll
    for (int fn = 0; fn < 4; fn++)
        #pragma unroll
        for (int r = 0; r < 4; r++) oacc[fn][r] = 0.f;

    for (int kc = 0; kc < NC; kc += 64) {
        __syncthreads();

        // stage K [key][d], V transposed [d][key], mask
        {
            int r  = tid >> 2;
            int j0 = tid & 3;
            const uint2* srcK = (const uint2*)(KV + (size_t)(b*NC + kc + r)*(2*CC) + h*HD);
            const uint2* srcV = (const uint2*)(KV + (size_t)(b*NC + kc + r)*(2*CC) + CC + h*HD);
            __half* Vh = (__half*)Vs;
            #pragma unroll
            for (int i = 0; i < 4; i++) {
                int j = j0 + 4*i;
                uint2 kv = srcK[j];
                Ks[r*SRH + 2*j]     = kv.x;
                Ks[r*SRH + 2*j + 1] = kv.y;
                uint2 vv = srcV[j];
                __half2 v0 = *(__half2*)&vv.x;
                __half2 v1 = *(__half2*)&vv.y;
                int d0 = 4*j;
                Vh[(d0 + 0)*(2*SRH) + r] = __low2half(v0);
                Vh[(d0 + 1)*(2*SRH) + r] = __high2half(v0);
                Vh[(d0 + 2)*(2*SRH) + r] = __low2half(v1);
                Vh[(d0 + 3)*(2*SRH) + r] = __high2half(v1);
            }
            if (tid < 64)
                Mv[tid] = (mask[b*NC + kc + tid] != 0) ? 0.f : -1e30f;
        }
        __syncthreads();

        // ---- S = Q @ K^T (rows 16wq.., keys 32wk..) ----
        float sfr[4][4];
        #pragma unroll
        for (int fn = 0; fn < 4; fn++)
            #pragma unroll
            for (int r = 0; r < 4; r++) sfr[fn][r] = 0.f;

        #pragma unroll
        for (int t = 0; t < 4; t++) {        // 4 k-steps of 16 over d=64
            const int u0 = 8*t + lc;
            uint32_t a0 = Qs[row0*SRH + u0];
            uint32_t a1 = Qs[row1*SRH + u0];
            uint32_t a2 = Qs[row0*SRH + u0 + 4];
            uint32_t a3 = Qs[row1*SRH + u0 + 4];
            #pragma unroll
            for (int fn = 0; fn < 4; fn++) {
                const uint32_t* p = Ks + (32*wk + 8*fn + lr)*SRH;
                MMA_F16(sfr[fn], a0, a1, a2, a3, p[u0], p[u0 + 4]);
            }
        }

        // ---- mask + row max ----
        float mx0 = -1e30f, mx1 = -1e30f;
        float mc0[4], mc1[4];
        #pragma unroll
        for (int fn = 0; fn < 4; fn++) {
            int col = 32*wk + 8*fn + 2*lc;
            mc0[fn] = Mv[col];
            mc1[fn] = Mv[col + 1];
            sfr[fn][0] += mc0[fn]; sfr[fn][1] += mc1[fn];
            sfr[fn][2] += mc0[fn]; sfr[fn][3] += mc1[fn];
            mx0 = fmaxf(mx0, fmaxf(sfr[fn][0], sfr[fn][1]));
            mx1 = fmaxf(mx1, fmaxf(sfr[fn][2], sfr[fn][3]));
        }
        mx0 = fmaxf(mx0, __shfl_xor_sync(0xffffffffu, mx0, 1));
        mx0 = fmaxf(mx0, __shfl_xor_sync(0xffffffffu, mx0, 2));
        mx1 = fmaxf(mx1, __shfl_xor_sync(0xffffffffu, mx1, 1));
        mx1 = fmaxf(mx1, __shfl_xor_sync(0xffffffffu, mx1, 2));
        if (lc == 0) {
            hm[wk*64 + row0] = mx0;
            hm[wk*64 + row1] = mx1;
        }
        __syncthreads();

        const float nm0 = fmaxf(m0, fmaxf(hm[row0], hm[64 + row0]));
        const float nm1 = fmaxf(m1, fmaxf(hm[row1], hm[64 + row1]));
        const float al0 = __expf(m0 - nm0);
        const float al1 = __expf(m1 - nm1);

        // ---- p = exp(s - m) * maskbit, write Ps (half2), partial sums ----
        float sum0 = 0.f, sum1 = 0.f;
        #pragma unroll
        for (int fn = 0; fn < 4; fn++) {
            float mb0 = (mc0[fn] == 0.f) ? 1.f : 0.f;
            float mb1 = (mc1[fn] == 0.f) ? 1.f : 0.f;
            float p0 = __expf(sfr[fn][0] - nm0) * mb0;
            float p1 = __expf(sfr[fn][1] - nm0) * mb1;
            float p2 = __expf(sfr[fn][2] - nm1) * mb0;
            float p3 = __expf(sfr[fn][3] - nm1) * mb1;
            sum0 += p0 + p1;
            sum1 += p2 + p3;
            int ui = 16*wk + 4*fn + lc;
            __half2 hp0 = __floats2half2_rn(p0, p1);
            __half2 hp1 = __floats2half2_rn(p2, p3);
            Ps[row0*SRH + ui] = *(uint32_t*)&hp0;
            Ps[row1*SRH + ui] = *(uint32_t*)&hp1;
        }
        sum0 += __shfl_xor_sync(0xffffffffu, sum0, 1);
        sum0 += __shfl_xor_sync(0xffffffffu, sum0, 2);
        sum1 += __shfl_xor_sync(0xffffffffu, sum1, 1);
        sum1 += __shfl_xor_sync(0xffffffffu, sum1, 2);
        if (lc == 0) {
            hs[wk*64 + row0] = sum0;
            hs[wk*64 + row1] = sum1;
        }

        #pragma unroll
        for (int fn = 0; fn < 4; fn++) {
            oacc[fn][0] *= al0; oacc[fn][1] *= al0;
            oacc[fn][2] *= al1; oacc[fn][3] *= al1;
        }
        __syncthreads();

        l0 = l0 * al0 + hs[row0] + hs[64 + row0];
        l1 = l1 * al1 + hs[row1] + hs[64 + row1];
        m0 = nm0; m1 = nm1;

        // ---- O += P @ V (rows 16wq.., d = 32wk..) ----
        #pragma unroll
        for (int t = 0; t < 4; t++) {        // k-steps of 16 over key=64
            const int u0 = 8*t + lc;
            uint32_t a0 = Ps[row0*SRH + u0];
            uint32_t a1 = Ps[row1*SRH + u0];
            uint32_t a2 = Ps[row0*SRH + u0 + 4];
            uint32_t a3 = Ps[row1*SRH + u0 + 4];
            #pragma unroll
            for (int fn = 0; fn < 4; fn++) {
                const uint32_t* p = Vs + (32*wk + 8*fn + lr)*SRH;
                MMA_F16(oacc[fn], a0, a1, a2, a3, p[u0], p[u0 + 4]);
            }
        }
    }

    // ---- normalize + write out (half) ----
    const float il0 = 1.f / l0;
    const float il1 = 1.f / l1;
    #pragma unroll
    for (int fn = 0; fn < 4; fn++) {
        int col = h*HD + 32*wk + 8*fn + 2*lc;
        *(__half2*)(OUT + (size_t)(b*NQ + q0 + row0)*CC + col) =
            __floats2half2_rn(oacc[fn][0]*il0, oacc[fn][1]*il0);
        *(__half2*)(OUT + (size_t)(b*NQ + q0 + row1)*CC + col) =
            __floats2half2_rn(oacc[fn][2]*il1, oacc[fn][3]*il1);
    }
}

// ---------------- orchestration ----------------
extern "C" void kernel_launch(void* const* d_in, const int* in_sizes, int n_in,
                              void* d_out, int out_size)
{
    const float* query   = (const float*)d_in[0];
    const float* context = (const float*)d_in[1];
    const int*   cmask   = (const int*)  d_in[2];
    const float* Wqp   = (const float*)d_in[3];
    const float* bqp   = (const float*)d_in[4];
    const float* Wcp   = (const float*)d_in[5];
    const float* bcp   = (const float*)d_in[6];
    const float* Wq    = (const float*)d_in[7];
    const float* bq    = (const float*)d_in[8];
    const float* Wkv   = (const float*)d_in[9];
    const float* bkv   = (const float*)d_in[10];
    const float* Wo    = (const float*)d_in[11];
    const float* bo    = (const float*)d_in[12];
    const float* g1    = (const float*)d_in[13];
    const float* beta1 = (const float*)d_in[14];
    const float* W1    = (const float*)d_in[15];
    const float* bf1   = (const float*)d_in[16];
    const float* W2    = (const float*)d_in[17];
    const float* bf2   = (const float*)d_in[18];
    const float* g2    = (const float*)d_in[19];
    const float* beta2 = (const float*)d_in[20];
    const float* gf    = (const float*)d_in[21];
    const float* betaf = (const float*)d_in[22];
    float* out = (float*)d_out;

    float  *bufQ;
    __half *bufC, *bufQN, *bufQH, *bufKV, *bufO, *bufF;
    __half *rQuery, *rCtx, *rWqp, *rWcp, *rWq, *rWkv, *rWo, *rW1, *rW2;
    cudaGetSymbolAddress((void**)&bufQ,  g_bufQ);
    cudaGetSymbolAddress((void**)&bufC,  g_bufC);
    cudaGetSymbolAddress((void**)&bufQN, g_bufQN);
    cudaGetSymbolAddress((void**)&bufQH, g_bufQH);
    cudaGetSymbolAddress((void**)&bufKV, g_bufKV);
    cudaGetSymbolAddress((void**)&bufO,  g_bufO);
    cudaGetSymbolAddress((void**)&bufF,  g_bufF);
    cudaGetSymbolAddress((void**)&rQuery, g_rQuery);
    cudaGetSymbolAddress((void**)&rCtx,   g_rCtx);
    cudaGetSymbolAddress((void**)&rWqp,   g_rWqp);
    cudaGetSymbolAddress((void**)&rWcp,   g_rWcp);
    cudaGetSymbolAddress((void**)&rWq,    g_rWq);
    cudaGetSymbolAddress((void**)&rWkv,   g_rWkv);
    cudaGetSymbolAddress((void**)&rWo,    g_rWo);
    cudaGetSymbolAddress((void**)&rW1,    g_rW1);
    cudaGetSymbolAddress((void**)&rW2,    g_rW2);

    const int smem_gemm = 4 * 16384;   // 64 KB, 4 stages
    cudaFuncSetAttribute(gemm_f16, cudaFuncAttributeMaxDynamicSharedMemorySize, smem_gemm);
    const int smem_attn = (4*64*SRH + 64 + 128 + 128) * 4;   // ~38.2 KB
    cudaFuncSetAttribute(attn_f16, cudaFuncAttributeMaxDynamicSharedMemorySize, smem_attn);

    const dim3 blk(256);
    const dim3 tb(32, 8);
    const int MQ = B_ * NQ;   // 2048
    const int MC = B_ * NC;   // 8192

    // ---- prep: halve activations; transpose+halve weights to [N][K] ----
    tohalf<<<(B_*NQ*DQ)/1024, 256>>>(query,   rQuery, B_*NQ*DQ);
    tohalf<<<(B_*NC*DC)/1024, 256>>>(context, rCtx,   B_*NC*DC);
    transpose_half<<<dim3(CC/32, DQ/32), tb>>>(Wqp, rWqp, DQ, CC);
    transpose_half<<<dim3(CC/32, DC/32), tb>>>(Wcp, rWcp, DC, CC);
    for (int l = 0; l < LL; l++) {
        transpose_half<<<dim3(CC/32,   CC/32), tb>>>(Wq  + (size_t)l*CC*CC,   rWq  + (size_t)l*CC*CC,   CC, CC);
        transpose_half<<<dim3(2*CC/32, CC/32), tb>>>(Wkv + (size_t)l*CC*2*CC, rWkv + (size_t)l*CC*2*CC, CC, 2*CC);
        transpose_half<<<dim3(CC/32,   CC/32), tb>>>(Wo  + (size_t)l*CC*CC,   rWo  + (size_t)l*CC*CC,   CC, CC);
        transpose_half<<<dim3(FF/32,   CC/32), tb>>>(W1  + (size_t)l*CC*FF,   rW1  + (size_t)l*CC*FF,   CC, FF);
        transpose_half<<<dim3(CC/32,   FF/32), tb>>>(W2  + (size_t)l*FF*CC,   rW2  + (size_t)l*FF*CC,   FF, CC);
    }

    // ---- main sequence ----
    gemm_f16<<<dim3(CC/128, MQ/128), blk, smem_gemm>>>(rQuery, rWqp, bqp, nullptr, bufQ, MQ, CC, DQ, 0);
    gemm_f16<<<dim3(CC/128, MC/128), blk, smem_gemm>>>(rCtx,   rWcp, bcp, nullptr, bufC, MC, CC, DC, 2);

    for (int l = 0; l < LL; l++) {
        ln_kernel<<<MQ, 256>>>(bufQ, g1 + l*CC, beta1 + l*CC, bufQN, 1);
        gemm_f16<<<dim3(CC/128,   MQ/128), blk, smem_gemm>>>(bufQN, rWq  + (size_t)l*CC*CC,   bq  + l*CC,   nullptr, bufQH, MQ, CC,   CC, 2);
        gemm_f16<<<dim3(2*CC/128, MC/128), blk, smem_gemm>>>(bufC,  rWkv + (size_t)l*CC*2*CC, bkv + l*2*CC, nullptr, bufKV, MC, 2*CC, CC, 2);
        attn_f16<<<dim3(NQ/64, HH, B_), blk, smem_attn>>>(bufQH, bufKV, cmask, bufO);
        gemm_f16<<<dim3(CC/128, MQ/128), blk, smem_gemm>>>(bufO, rWo + (size_t)l*CC*CC, bo + l*CC, bufQ, bufQ, MQ, CC, CC, 0);
        ln_kernel<<<MQ, 256>>>(bufQ, g2 + l*CC, beta2 + l*CC, bufQN, 1);
        gemm_f16<<<dim3(FF/128, MQ/128), blk, smem_gemm>>>(bufQN, rW1 + (size_t)l*CC*FF, bf1 + l*FF, nullptr, bufF, MQ, FF, CC, 3);
        gemm_f16<<<dim3(CC/128, MQ/128), blk, smem_gemm>>>(bufF,  rW2 + (size_t)l*FF*CC, bf2 + l*CC, bufQ,   bufQ, MQ, CC, FF, 0);
    }
    ln_kernel<<<MQ, 256>>>(bufQ, gf, betaf, out, 0);
}